// round 8
// baseline (speedup 1.0000x reference)
#include <cuda_runtime.h>
#include <cuda_bf16.h>
#include <stdint.h>
#include <math.h>

// Problem constants
#define D       512
#define NQKV    1536
#define MV      16384       // unique v-token rows (B*S*16)
#define MTOK    16448       // + 64 a-token rows
#define MTOKPAD 16512       // padded to tile multiple
#define NROWS   32768

// Output layout offsets (floats)
#define OFF1    4194304     // vf_o
#define OFF2    8388608     // ap_o
#define OFF3    8404992     // af_o

// Scratch
__device__ __nv_bfloat16 g_tok_hi[(size_t)MTOKPAD * D];
__device__ __nv_bfloat16 g_tok_lo[(size_t)MTOKPAD * D];
__device__ __nv_bfloat16 g_wq_hi[(size_t)D * NQKV];
__device__ __nv_bfloat16 g_wq_lo[(size_t)D * NQKV];
__device__ __nv_bfloat16 g_wp_hi[(size_t)D * D];
__device__ __nv_bfloat16 g_wp_lo[(size_t)D * D];
__device__ float         g_qkv[(size_t)MTOK * NQKV];
__device__ __nv_bfloat16 g_o_hi[(size_t)NROWS * D];
__device__ __nv_bfloat16 g_o_lo[(size_t)NROWS * D];

// ---------------------------------------------------------------------------
__device__ __forceinline__ uint32_t smem_u32(const void* p) {
    return (uint32_t)__cvta_generic_to_shared(p);
}

#define LDSM_X4(r0,r1,r2,r3,addr) \
    asm volatile("ldmatrix.sync.aligned.m8n8.x4.shared.b16 {%0,%1,%2,%3}, [%4];" \
        : "=r"(r0),"=r"(r1),"=r"(r2),"=r"(r3) : "r"(addr))

#define LDSM_X4_T(r0,r1,r2,r3,addr) \
    asm volatile("ldmatrix.sync.aligned.m8n8.x4.trans.shared.b16 {%0,%1,%2,%3}, [%4];" \
        : "=r"(r0),"=r"(r1),"=r"(r2),"=r"(r3) : "r"(addr))

#define MMA16816(d, a, b) \
    asm volatile("mma.sync.aligned.m16n8k16.row.col.f32.bf16.bf16.f32 " \
        "{%0,%1,%2,%3},{%4,%5,%6,%7},{%8,%9},{%0,%1,%2,%3};" \
        : "+f"(d[0]),"+f"(d[1]),"+f"(d[2]),"+f"(d[3]) \
        : "r"(a[0]),"r"(a[1]),"r"(a[2]),"r"(a[3]),"r"(b[0]),"r"(b[1]))

#define CP16(dst, src) \
    asm volatile("cp.async.cg.shared.global [%0], [%1], 16;" :: "r"(dst), "l"(src))
#define CP_COMMIT() asm volatile("cp.async.commit_group;")
#define CP_WAIT(n)  asm volatile("cp.async.wait_group %0;" :: "n"(n))

__device__ __forceinline__ void cvt_hilo(float x, __nv_bfloat16& h, __nv_bfloat16& l) {
    h = __float2bfloat16(x);
    l = __float2bfloat16(x - __bfloat162float(h));
}

// Token row gather: mode 0 = v-tokens, mode 1 = a-tokens
__device__ __forceinline__ const float* token_ptr(int r, int mode,
    const float* __restrict__ p0, const float* __restrict__ p1)
{
    if (mode == 0) {
        int b = r >> 12;
        int rem = r & 4095;
        int s = rem >> 4;
        int t = rem & 15;
        if (t < 8)  return p0 + ((size_t)((((b << 3) + t) << 8) + s) << 9);
        else        return p1 + ((size_t)((((b << 3) + (t - 8)) << 8) + s) << 9);
    } else {
        int b = r >> 4;
        int t = r & 15;
        if (t < 8)  return p0 + ((size_t)((b << 3) + t) << 9);
        else        return p1 + ((size_t)((b << 3) + (t - 8)) << 9);
    }
}

// ---------------------------------------------------------------------------
// Pre-conversion kernels
// ---------------------------------------------------------------------------
__global__ void __launch_bounds__(256) conv_tokens(
    const float* __restrict__ v_p, const float* __restrict__ v_f,
    const float* __restrict__ a_p, const float* __restrict__ a_f)
{
    int idx = blockIdx.x * 256 + threadIdx.x;    // one float4 per thread
    int row = idx >> 7;
    int c4  = (idx & 127) << 2;
    if (row >= MTOK) return;
    const float* src = (row < MV) ? token_ptr(row, 0, v_p, v_f)
                                  : token_ptr(row - MV, 1, a_p, a_f);
    float4 v = *(const float4*)(src + c4);
    __nv_bfloat16 h[4], l[4];
    cvt_hilo(v.x, h[0], l[0]); cvt_hilo(v.y, h[1], l[1]);
    cvt_hilo(v.z, h[2], l[2]); cvt_hilo(v.w, h[3], l[3]);
    size_t off = (size_t)row * D + c4;
    *(__nv_bfloat162*)(g_tok_hi + off)     = __nv_bfloat162(h[0], h[1]);
    *(__nv_bfloat162*)(g_tok_hi + off + 2) = __nv_bfloat162(h[2], h[3]);
    *(__nv_bfloat162*)(g_tok_lo + off)     = __nv_bfloat162(l[0], l[1]);
    *(__nv_bfloat162*)(g_tok_lo + off + 2) = __nv_bfloat162(l[2], l[3]);
}

__global__ void __launch_bounds__(256) conv_weights(
    const float* __restrict__ Wq, const float* __restrict__ Wp)
{
    int idx = blockIdx.x * 256 + threadIdx.x;    // one float4 per thread
    const int NQ4 = (D * NQKV) / 4;              // 196608
    const float* src;
    __nv_bfloat16 *dh, *dl;
    size_t off;
    if (idx < NQ4)      { src = Wq; dh = g_wq_hi; dl = g_wq_lo; off = (size_t)idx << 2; }
    else                { idx -= NQ4;
                          if (idx >= (D * D) / 4) return;
                          src = Wp; dh = g_wp_hi; dl = g_wp_lo; off = (size_t)idx << 2; }
    float4 v = *(const float4*)(src + off);
    __nv_bfloat16 h[4], l[4];
    cvt_hilo(v.x, h[0], l[0]); cvt_hilo(v.y, h[1], l[1]);
    cvt_hilo(v.z, h[2], l[2]); cvt_hilo(v.w, h[3], l[3]);
    *(__nv_bfloat162*)(dh + off)     = __nv_bfloat162(h[0], h[1]);
    *(__nv_bfloat162*)(dh + off + 2) = __nv_bfloat162(h[2], h[3]);
    *(__nv_bfloat162*)(dl + off)     = __nv_bfloat162(l[0], l[1]);
    *(__nv_bfloat162*)(dl + off + 2) = __nv_bfloat162(l[2], l[3]);
}

// ---------------------------------------------------------------------------
// Pipelined bf16x3 GEMM: 128x128 tile, BK=32, 3-stage cp.async, 256 threads.
// Stage layout (bytes): Ahi[128][40], Alo, Bhi[32][136], Blo
// ---------------------------------------------------------------------------
#define STG_A_HI   0
#define STG_A_LO   10240
#define STG_B_HI   20480
#define STG_B_LO   29184
#define STG_STRIDE 37888
#define NSTAGE     3
#define SMEM_BYTES (NSTAGE * STG_STRIDE)
#define NSLAB      16

__device__ __forceinline__ void prefetch_slab(
    uint32_t stg,
    const __nv_bfloat16* __restrict__ Ahi, const __nv_bfloat16* __restrict__ Alo,
    const __nv_bfloat16* __restrict__ Bhi, const __nv_bfloat16* __restrict__ Blo,
    int ldb, int bn, int k0, int tid)
{
    #pragma unroll
    for (int t = 0; t < 2; ++t) {
        int q  = tid + (t << 8);              // 0..511
        int r  = q >> 2, kc = (q & 3) << 3;   // A: 128 rows x 4 chunks
        uint32_t ao = (uint32_t)(r * 80 + (kc << 1));
        size_t asrc = (size_t)r * D + k0 + kc;
        CP16(stg + STG_A_HI + ao, Ahi + asrc);
        CP16(stg + STG_A_LO + ao, Alo + asrc);
        int br = q >> 4, nc = (q & 15) << 3;  // B: 32 rows x 16 chunks
        uint32_t bo = (uint32_t)(br * 272 + (nc << 1));
        size_t bsrc = (size_t)(k0 + br) * ldb + bn + nc;
        CP16(stg + STG_B_HI + bo, Bhi + bsrc);
        CP16(stg + STG_B_LO + bo, Blo + bsrc);
    }
}

__device__ __forceinline__ void compute_slab(
    char* stg, int m0, int n0, int lane, float (&acc)[2][8][4])
{
    uint32_t ah[2][4], al[2][4], bh[8][2], bl[8][2];
    #pragma unroll
    for (int ks = 0; ks < 2; ++ks) {
        const int k0   = ks << 4;
        const int arow = lane & 15;
        const int acol = k0 + ((lane >> 4) << 3);
        #pragma unroll
        for (int mt = 0; mt < 2; ++mt) {
            uint32_t ad = smem_u32(stg + STG_A_HI + (m0 + (mt << 4) + arow) * 80 + acol * 2);
            LDSM_X4(ah[mt][0], ah[mt][1], ah[mt][2], ah[mt][3], ad);
            uint32_t ad2 = smem_u32(stg + STG_A_LO + (m0 + (mt << 4) + arow) * 80 + acol * 2);
            LDSM_X4(al[mt][0], al[mt][1], al[mt][2], al[mt][3], ad2);
        }
        #pragma unroll
        for (int p = 0; p < 4; ++p) {
            const int ncol = n0 + (p << 4) + ((lane >> 4) << 3);
            uint32_t bd = smem_u32(stg + STG_B_HI + (k0 + (lane & 15)) * 272 + ncol * 2);
            LDSM_X4_T(bh[2*p][0], bh[2*p][1], bh[2*p+1][0], bh[2*p+1][1], bd);
            uint32_t bd2 = smem_u32(stg + STG_B_LO + (k0 + (lane & 15)) * 272 + ncol * 2);
            LDSM_X4_T(bl[2*p][0], bl[2*p][1], bl[2*p+1][0], bl[2*p+1][1], bd2);
        }
        #pragma unroll
        for (int mt = 0; mt < 2; ++mt)
            #pragma unroll
            for (int nt = 0; nt < 8; ++nt) {
                MMA16816(acc[mt][nt], ah[mt], bh[nt]);
                MMA16816(acc[mt][nt], ah[mt], bl[nt]);
                MMA16816(acc[mt][nt], al[mt], bh[nt]);
            }
    }
}

// 3-stage pipeline: one __syncthreads per slab. The barrier at the top of
// iteration ks orders compute(ks-1) (same buffer as prefetch(ks+2)) before
// the prefetch, and makes slab ks's cp.async data visible block-wide.
#define GEMM_MAIN(AHI, ALO, BHI, BLO, LDB, BN)                                   \
    extern __shared__ char smem[];                                               \
    const uint32_t sbase = smem_u32(smem);                                       \
    const int tid  = threadIdx.x;                                                \
    const int lane = tid & 31;                                                   \
    const int w    = tid >> 5;                                                   \
    const int m0   = (w >> 1) << 5;                                              \
    const int n0   = (w & 1) << 6;                                               \
    float acc[2][8][4];                                                          \
    _Pragma("unroll")                                                            \
    for (int mt = 0; mt < 2; ++mt)                                               \
        _Pragma("unroll")                                                        \
        for (int nt = 0; nt < 8; ++nt)                                           \
            _Pragma("unroll")                                                    \
            for (int e = 0; e < 4; ++e) acc[mt][nt][e] = 0.f;                    \
    prefetch_slab(sbase + 0 * STG_STRIDE, AHI, ALO, BHI, BLO, LDB, BN, 0, tid);  \
    CP_COMMIT();                                                                 \
    prefetch_slab(sbase + 1 * STG_STRIDE, AHI, ALO, BHI, BLO, LDB, BN, 32, tid); \
    CP_COMMIT();                                                                 \
    {                                                                            \
        int stg_w = 2, stg_r = 0;                                                \
        for (int ks = 0; ks < NSLAB; ++ks) {                                     \
            if (ks + 1 < NSLAB) { CP_WAIT(1); } else { CP_WAIT(0); }             \
            __syncthreads();                                                     \
            if (ks + 2 < NSLAB) {                                                \
                prefetch_slab(sbase + stg_w * STG_STRIDE,                        \
                              AHI, ALO, BHI, BLO, LDB, BN, (ks + 2) * 32, tid);  \
                CP_COMMIT();                                                     \
                if (++stg_w == NSTAGE) stg_w = 0;                                \
            }                                                                    \
            compute_slab(smem + stg_r * STG_STRIDE, m0, n0, lane, acc);          \
            if (++stg_r == NSTAGE) stg_r = 0;                                    \
        }                                                                        \
    }

// ---------------------------------------------------------------------------
// QKV GEMM: g_qkv[MTOK,1536] = tok[MTOKPAD,512] @ W_qkv[512,1536]
// ---------------------------------------------------------------------------
__global__ void __launch_bounds__(256) qkv_gemm(void)
{
    const int bm = blockIdx.y << 7;
    const int bn = blockIdx.x << 7;
    GEMM_MAIN(g_tok_hi + (size_t)bm * D, g_tok_lo + (size_t)bm * D,
              g_wq_hi, g_wq_lo, NQKV, bn)

    #pragma unroll
    for (int mt = 0; mt < 2; ++mt) {
        int r0 = bm + m0 + (mt << 4) + (lane >> 2);
        #pragma unroll
        for (int nt = 0; nt < 8; ++nt) {
            int c = bn + n0 + (nt << 3) + ((lane & 3) << 1);
            if (r0 < MTOK)
                *(float2*)(g_qkv + (size_t)r0 * NQKV + c) =
                    make_float2(acc[mt][nt][0], acc[mt][nt][1]);
            if (r0 + 8 < MTOK)
                *(float2*)(g_qkv + (size_t)(r0 + 8) * NQKV + c) =
                    make_float2(acc[mt][nt][2], acc[mt][nt][3]);
        }
    }
}

// ---------------------------------------------------------------------------
// Proj GEMM: (attn out)[32768,512] @ W_proj[512,512] + bias, fused scatter.
// ---------------------------------------------------------------------------
__device__ __forceinline__ void scatter_out(float* __restrict__ out, int r, int c, float v)
{
    int bs = r >> 5, t = r & 31, b = bs >> 8, s = bs & 255;
    if (t < 8) {
        out[((size_t)((((b << 3) + t) << 8) + s) << 9) + c] = v;
    } else if (t < 16) {
        out[OFF1 + ((size_t)((((b << 3) + (t - 8)) << 8) + s) << 9) + c] = v;
    } else if (t < 24) {
        atomicAdd(out + OFF2 + (((b << 3) + (t - 16)) << 9) + c, v * (1.f / 256.f));
    } else {
        atomicAdd(out + OFF3 + (((b << 3) + (t - 24)) << 9) + c, v * (1.f / 256.f));
    }
}

__global__ void __launch_bounds__(256) proj_gemm(
    const float* __restrict__ bias, float* __restrict__ out)
{
    const int bm = blockIdx.y << 7;
    const int bn = blockIdx.x << 7;
    GEMM_MAIN(g_o_hi + (size_t)bm * D, g_o_lo + (size_t)bm * D,
              g_wp_hi, g_wp_lo, D, bn)

    #pragma unroll
    for (int mt = 0; mt < 2; ++mt) {
        int r0 = bm + m0 + (mt << 4) + (lane >> 2);
        #pragma unroll
        for (int nt = 0; nt < 8; ++nt) {
            int c = bn + n0 + (nt << 3) + ((lane & 3) << 1);
            float b0 = bias[c], b1 = bias[c + 1];
            scatter_out(out, r0,     c,     acc[mt][nt][0] + b0);
            scatter_out(out, r0,     c + 1, acc[mt][nt][1] + b1);
            scatter_out(out, r0 + 8, c,     acc[mt][nt][2] + b0);
            scatter_out(out, r0 + 8, c + 1, acc[mt][nt][3] + b1);
        }
    }
}

// ---------------------------------------------------------------------------
// Attention: one block per (bs, head). 32x32 over hd=64, RoPE fused.
// Register-blocked (R6 scalar layout — measured best).
// ---------------------------------------------------------------------------
__global__ void __launch_bounds__(128) attn_kernel()
{
    __shared__ float Qs[32][65];
    __shared__ float Ks[32][65];
    __shared__ float Vs[32][65];
    __shared__ float Ss[32][33];

    const int tid = threadIdx.x;
    const int bh  = blockIdx.x;
    const int bs  = bh >> 3;
    const int h   = bh & 7;
    const int b   = bs >> 8;

    #pragma unroll
    for (int p = 0; p < 4; ++p) {
        int idx = tid + (p << 7);
        int t   = idx >> 4;
        int c4  = (idx & 15) << 2;
        int row = (t < 16) ? ((bs << 4) + t) : (MV + (b << 4) + (t - 16));
        const float* qp = g_qkv + (size_t)row * NQKV + (h << 6) + c4;
        float4 q = *(const float4*)(qp);
        float4 k = *(const float4*)(qp + 512);
        float4 v = *(const float4*)(qp + 1024);
        Qs[t][c4 + 0] = q.x; Qs[t][c4 + 1] = q.y; Qs[t][c4 + 2] = q.z; Qs[t][c4 + 3] = q.w;
        Ks[t][c4 + 0] = k.x; Ks[t][c4 + 1] = k.y; Ks[t][c4 + 2] = k.z; Ks[t][c4 + 3] = k.w;
        Vs[t][c4 + 0] = v.x; Vs[t][c4 + 1] = v.y; Vs[t][c4 + 2] = v.z; Vs[t][c4 + 3] = v.w;
    }
    __syncthreads();

    // RoPE in-place on Q,K
    #pragma unroll
    for (int p = 0; p < 8; ++p) {
        int idx = tid + (p << 7);
        int t = idx >> 5;
        int j = idx & 31;
        float inv = exp2f(-0.41524101186091903f * (float)j);
        float ang = (float)t * inv;
        float sn, cs;
        sincosf(ang, &sn, &cs);
        float q1 = Qs[t][j], q2 = Qs[t][j + 32];
        Qs[t][j]      = q1 * cs - q2 * sn;
        Qs[t][j + 32] = q2 * cs + q1 * sn;
        float k1 = Ks[t][j], k2 = Ks[t][j + 32];
        Ks[t][j]      = k1 * cs - k2 * sn;
        Ks[t][j + 32] = k2 * cs + k1 * sn;
    }
    __syncthreads();

    // S = (Q K^T) * scale: 2x4 register block per thread
    {
        const int r0 = (tid >> 3) << 1;     // 0,2,..,30
        const int c0 = (tid & 7) << 2;      // 0,4,..,28
        float s[2][4] = {{0.f,0.f,0.f,0.f},{0.f,0.f,0.f,0.f}};
        #pragma unroll
        for (int c = 0; c < 64; ++c) {
            float q0 = Qs[r0][c], q1 = Qs[r0 + 1][c];
            float k0 = Ks[c0][c], k1 = Ks[c0+1][c], k2 = Ks[c0+2][c], k3 = Ks[c0+3][c];
            s[0][0] += q0*k0; s[0][1] += q0*k1; s[0][2] += q0*k2; s[0][3] += q0*k3;
            s[1][0] += q1*k0; s[1][1] += q1*k1; s[1][2] += q1*k2; s[1][3] += q1*k3;
        }
        #pragma unroll
        for (int i = 0; i < 2; ++i)
            #pragma unroll
            for (int j = 0; j < 4; ++j)
                Ss[r0 + i][c0 + j] = s[i][j] * 0.125f;
    }
    __syncthreads();

    // Row softmax
    const int lane = tid & 31;
    const int w    = tid >> 5;
    #pragma unroll
    for (int rr = 0; rr < 8; ++rr) {
        int i = (w << 3) + rr;
        float val = Ss[i][lane];
        float m = val;
        #pragma unroll
        for (int o = 16; o > 0; o >>= 1) m = fmaxf(m, __shfl_xor_sync(0xffffffffu, m, o));
        float e = expf(val - m);
        float sum = e;
        #pragma unroll
        for (int o = 16; o > 0; o >>= 1) sum += __shfl_xor_sync(0xffffffffu, sum, o);
        Ss[i][lane] = e / sum;
    }
    __syncthreads();

    // O = P @ V: 4x4 register block per thread -> bf16 hi/lo
    {
        const int r0 = (tid >> 4) << 2;     // 0,4,..,28
        const int c0 = (tid & 15) << 2;     // 0,4,..,60
        float o[4][4];
        #pragma unroll
        for (int i = 0; i < 4; ++i)
            #pragma unroll
            for (int j = 0; j < 4; ++j) o[i][j] = 0.f;
        #pragma unroll
        for (int j = 0; j < 32; ++j) {
            float v0 = Vs[j][c0], v1 = Vs[j][c0+1], v2 = Vs[j][c0+2], v3 = Vs[j][c0+3];
            float s0 = Ss[r0][j], s1 = Ss[r0+1][j], s2 = Ss[r0+2][j], s3 = Ss[r0+3][j];
            o[0][0] += s0*v0; o[0][1] += s0*v1; o[0][2] += s0*v2; o[0][3] += s0*v3;
            o[1][0] += s1*v0; o[1][1] += s1*v1; o[1][2] += s1*v2; o[1][3] += s1*v3;
            o[2][0] += s2*v0; o[2][1] += s2*v1; o[2][2] += s2*v2; o[2][3] += s2*v3;
            o[3][0] += s3*v0; o[3][1] += s3*v1; o[3][2] += s3*v2; o[3][3] += s3*v3;
        }
        #pragma unroll
        for (int i = 0; i < 4; ++i) {
            __nv_bfloat16 h0,l0,h1,l1,h2,l2,h3,l3;
            cvt_hilo(o[i][0], h0, l0); cvt_hilo(o[i][1], h1, l1);
            cvt_hilo(o[i][2], h2, l2); cvt_hilo(o[i][3], h3, l3);
            size_t off = (size_t)((bs << 5) + r0 + i) * D + (h << 6) + c0;
            *(__nv_bfloat162*)(g_o_hi + off)     = __nv_bfloat162(h0, h1);
            *(__nv_bfloat162*)(g_o_hi + off + 2) = __nv_bfloat162(h2, h3);
            *(__nv_bfloat162*)(g_o_lo + off)     = __nv_bfloat162(l0, l1);
            *(__nv_bfloat162*)(g_o_lo + off + 2) = __nv_bfloat162(l2, l3);
        }
    }
}

// ---------------------------------------------------------------------------
__global__ void zero_tail_kernel(float* __restrict__ out)
{
    int i = blockIdx.x * 256 + threadIdx.x;
    if (i < 32768) out[OFF2 + i] = 0.f;
}

// ---------------------------------------------------------------------------
extern "C" void kernel_launch(void* const* d_in, const int* in_sizes, int n_in,
                              void* d_out, int out_size)
{
    const float* v_p    = (const float*)d_in[0];
    const float* v_f    = (const float*)d_in[1];
    const float* a_p    = (const float*)d_in[2];
    const float* a_f    = (const float*)d_in[3];
    const float* W_qkv  = (const float*)d_in[4];
    const float* W_proj = (const float*)d_in[5];
    const float* b_proj = (const float*)d_in[6];
    float* out = (float*)d_out;

    cudaFuncSetAttribute(qkv_gemm,  cudaFuncAttributeMaxDynamicSharedMemorySize, SMEM_BYTES);
    cudaFuncSetAttribute(proj_gemm, cudaFuncAttributeMaxDynamicSharedMemorySize, SMEM_BYTES);

    conv_weights<<<1024, 256>>>(W_qkv, W_proj);
    conv_tokens<<<8224, 256>>>(v_p, v_f, a_p, a_f);

    qkv_gemm<<<dim3(12, 129), 256, SMEM_BYTES>>>();

    attn_kernel<<<8192, 128>>>();

    zero_tail_kernel<<<128, 256>>>(out);
    proj_gemm<<<dim3(4, 256), 256, SMEM_BYTES>>>(b_proj, out);
}

// round 9
// speedup vs baseline: 1.1136x; 1.1136x over previous
#include <cuda_runtime.h>
#include <cuda_bf16.h>
#include <stdint.h>
#include <math.h>

// Problem constants
#define D       512
#define NQKV    1536
#define MV      16384       // unique v-token rows (B*S*16)
#define MTOK    16448       // + 64 a-token rows
#define MTOKPAD 16512       // padded to tile multiple
#define NROWS   32768

// Output layout offsets (floats)
#define OFF1    4194304     // vf_o
#define OFF2    8388608     // ap_o
#define OFF3    8404992     // af_o

// Scratch
__device__ __nv_bfloat16 g_tok_hi[(size_t)MTOKPAD * D];
__device__ __nv_bfloat16 g_tok_lo[(size_t)MTOKPAD * D];
__device__ __nv_bfloat16 g_wq_hi[(size_t)D * NQKV];
__device__ __nv_bfloat16 g_wq_lo[(size_t)D * NQKV];
__device__ __nv_bfloat16 g_wp_hi[(size_t)D * D];
__device__ __nv_bfloat16 g_wp_lo[(size_t)D * D];
__device__ float         g_qkv[(size_t)MTOK * NQKV];
__device__ __nv_bfloat16 g_o_hi[(size_t)NROWS * D];
__device__ __nv_bfloat16 g_o_lo[(size_t)NROWS * D];
__device__ float2        g_rope[1024];   // (sin, cos) for t*32+j

// ---------------------------------------------------------------------------
__device__ __forceinline__ uint32_t smem_u32(const void* p) {
    return (uint32_t)__cvta_generic_to_shared(p);
}

#define LDSM_X4(r0,r1,r2,r3,addr) \
    asm volatile("ldmatrix.sync.aligned.m8n8.x4.shared.b16 {%0,%1,%2,%3}, [%4];" \
        : "=r"(r0),"=r"(r1),"=r"(r2),"=r"(r3) : "r"(addr))

#define LDSM_X4_T(r0,r1,r2,r3,addr) \
    asm volatile("ldmatrix.sync.aligned.m8n8.x4.trans.shared.b16 {%0,%1,%2,%3}, [%4];" \
        : "=r"(r0),"=r"(r1),"=r"(r2),"=r"(r3) : "r"(addr))

#define MMA16816(d, a, b) \
    asm volatile("mma.sync.aligned.m16n8k16.row.col.f32.bf16.bf16.f32 " \
        "{%0,%1,%2,%3},{%4,%5,%6,%7},{%8,%9},{%0,%1,%2,%3};" \
        : "+f"(d[0]),"+f"(d[1]),"+f"(d[2]),"+f"(d[3]) \
        : "r"(a[0]),"r"(a[1]),"r"(a[2]),"r"(a[3]),"r"(b[0]),"r"(b[1]))

#define CP16(dst, src) \
    asm volatile("cp.async.cg.shared.global [%0], [%1], 16;" :: "r"(dst), "l"(src))
#define CP_COMMIT() asm volatile("cp.async.commit_group;")
#define CP_WAIT(n)  asm volatile("cp.async.wait_group %0;" :: "n"(n))

__device__ __forceinline__ void cvt_hilo(float x, __nv_bfloat16& h, __nv_bfloat16& l) {
    h = __float2bfloat16(x);
    l = __float2bfloat16(x - __bfloat162float(h));
}

// Token row gather: mode 0 = v-tokens, mode 1 = a-tokens
__device__ __forceinline__ const float* token_ptr(int r, int mode,
    const float* __restrict__ p0, const float* __restrict__ p1)
{
    if (mode == 0) {
        int b = r >> 12;
        int rem = r & 4095;
        int s = rem >> 4;
        int t = rem & 15;
        if (t < 8)  return p0 + ((size_t)((((b << 3) + t) << 8) + s) << 9);
        else        return p1 + ((size_t)((((b << 3) + (t - 8)) << 8) + s) << 9);
    } else {
        int b = r >> 4;
        int t = r & 15;
        if (t < 8)  return p0 + ((size_t)((b << 3) + t) << 9);
        else        return p1 + ((size_t)((b << 3) + (t - 8)) << 9);
    }
}

// ---------------------------------------------------------------------------
// Pre-conversion kernels
// ---------------------------------------------------------------------------
__global__ void __launch_bounds__(256) conv_tokens(
    const float* __restrict__ v_p, const float* __restrict__ v_f,
    const float* __restrict__ a_p, const float* __restrict__ a_f)
{
    int idx = blockIdx.x * 256 + threadIdx.x;    // one float4 per thread
    int row = idx >> 7;
    int c4  = (idx & 127) << 2;
    if (row >= MTOK) return;
    const float* src = (row < MV) ? token_ptr(row, 0, v_p, v_f)
                                  : token_ptr(row - MV, 1, a_p, a_f);
    float4 v = *(const float4*)(src + c4);
    __nv_bfloat16 h[4], l[4];
    cvt_hilo(v.x, h[0], l[0]); cvt_hilo(v.y, h[1], l[1]);
    cvt_hilo(v.z, h[2], l[2]); cvt_hilo(v.w, h[3], l[3]);
    size_t off = (size_t)row * D + c4;
    *(__nv_bfloat162*)(g_tok_hi + off)     = __nv_bfloat162(h[0], h[1]);
    *(__nv_bfloat162*)(g_tok_hi + off + 2) = __nv_bfloat162(h[2], h[3]);
    *(__nv_bfloat162*)(g_tok_lo + off)     = __nv_bfloat162(l[0], l[1]);
    *(__nv_bfloat162*)(g_tok_lo + off + 2) = __nv_bfloat162(l[2], l[3]);
}

__global__ void __launch_bounds__(256) conv_weights(
    const float* __restrict__ Wq, const float* __restrict__ Wp)
{
    int idx = blockIdx.x * 256 + threadIdx.x;    // one float4 per thread
    const int NQ4 = (D * NQKV) / 4;              // 196608
    const float* src;
    __nv_bfloat16 *dh, *dl;
    size_t off;
    if (idx < NQ4)      { src = Wq; dh = g_wq_hi; dl = g_wq_lo; off = (size_t)idx << 2; }
    else                { idx -= NQ4;
                          if (idx >= (D * D) / 4) return;
                          src = Wp; dh = g_wp_hi; dl = g_wp_lo; off = (size_t)idx << 2; }
    float4 v = *(const float4*)(src + off);
    __nv_bfloat16 h[4], l[4];
    cvt_hilo(v.x, h[0], l[0]); cvt_hilo(v.y, h[1], l[1]);
    cvt_hilo(v.z, h[2], l[2]); cvt_hilo(v.w, h[3], l[3]);
    *(__nv_bfloat162*)(dh + off)     = __nv_bfloat162(h[0], h[1]);
    *(__nv_bfloat162*)(dh + off + 2) = __nv_bfloat162(h[2], h[3]);
    *(__nv_bfloat162*)(dl + off)     = __nv_bfloat162(l[0], l[1]);
    *(__nv_bfloat162*)(dl + off + 2) = __nv_bfloat162(l[2], l[3]);
}

// RoPE sin/cos table: entry t*32+j = (sin, cos) of t * 10000^(-j/32)
__global__ void rope_table_kernel(void)
{
    int idx = threadIdx.x + blockIdx.x * 256;
    if (idx >= 1024) return;
    int t = idx >> 5;
    int j = idx & 31;
    float inv = exp2f(-0.41524101186091903f * (float)j);
    float ang = (float)t * inv;
    float sn, cs;
    sincosf(ang, &sn, &cs);
    g_rope[idx] = make_float2(sn, cs);
}

// ---------------------------------------------------------------------------
// Pipelined bf16x3 GEMM: 128x128 tile, BK=32, 2-stage cp.async, 256 threads.
// Stage layout (bytes): Ahi[128][40], Alo, Bhi[32][136], Blo
// ---------------------------------------------------------------------------
#define STG_A_HI   0
#define STG_A_LO   10240
#define STG_B_HI   20480
#define STG_B_LO   29184
#define STG_STRIDE 37888
#define SMEM_BYTES (2 * STG_STRIDE)
#define NSLAB      16

__device__ __forceinline__ void prefetch_slab(
    uint32_t stg,
    const __nv_bfloat16* __restrict__ Ahi, const __nv_bfloat16* __restrict__ Alo,
    const __nv_bfloat16* __restrict__ Bhi, const __nv_bfloat16* __restrict__ Blo,
    int ldb, int bn, int k0, int tid)
{
    #pragma unroll
    for (int t = 0; t < 2; ++t) {
        int q  = tid + (t << 8);              // 0..511
        int r  = q >> 2, kc = (q & 3) << 3;   // A: 128 rows x 4 chunks
        uint32_t ao = (uint32_t)(r * 80 + (kc << 1));
        size_t asrc = (size_t)r * D + k0 + kc;
        CP16(stg + STG_A_HI + ao, Ahi + asrc);
        CP16(stg + STG_A_LO + ao, Alo + asrc);
        int br = q >> 4, nc = (q & 15) << 3;  // B: 32 rows x 16 chunks
        uint32_t bo = (uint32_t)(br * 272 + (nc << 1));
        size_t bsrc = (size_t)(k0 + br) * ldb + bn + nc;
        CP16(stg + STG_B_HI + bo, Bhi + bsrc);
        CP16(stg + STG_B_LO + bo, Blo + bsrc);
    }
}

__device__ __forceinline__ void compute_slab(
    char* stg, int m0, int n0, int lane, float (&acc)[2][8][4])
{
    uint32_t ah[2][4], al[2][4], bh[8][2], bl[8][2];
    #pragma unroll
    for (int ks = 0; ks < 2; ++ks) {
        const int k0   = ks << 4;
        const int arow = lane & 15;
        const int acol = k0 + ((lane >> 4) << 3);
        #pragma unroll
        for (int mt = 0; mt < 2; ++mt) {
            uint32_t ad = smem_u32(stg + STG_A_HI + (m0 + (mt << 4) + arow) * 80 + acol * 2);
            LDSM_X4(ah[mt][0], ah[mt][1], ah[mt][2], ah[mt][3], ad);
            uint32_t ad2 = smem_u32(stg + STG_A_LO + (m0 + (mt << 4) + arow) * 80 + acol * 2);
            LDSM_X4(al[mt][0], al[mt][1], al[mt][2], al[mt][3], ad2);
        }
        #pragma unroll
        for (int p = 0; p < 4; ++p) {
            const int ncol = n0 + (p << 4) + ((lane >> 4) << 3);
            uint32_t bd = smem_u32(stg + STG_B_HI + (k0 + (lane & 15)) * 272 + ncol * 2);
            LDSM_X4_T(bh[2*p][0], bh[2*p][1], bh[2*p+1][0], bh[2*p+1][1], bd);
            uint32_t bd2 = smem_u32(stg + STG_B_LO + (k0 + (lane & 15)) * 272 + ncol * 2);
            LDSM_X4_T(bl[2*p][0], bl[2*p][1], bl[2*p+1][0], bl[2*p+1][1], bd2);
        }
        #pragma unroll
        for (int mt = 0; mt < 2; ++mt)
            #pragma unroll
            for (int nt = 0; nt < 8; ++nt) {
                MMA16816(acc[mt][nt], ah[mt], bh[nt]);
                MMA16816(acc[mt][nt], ah[mt], bl[nt]);
                MMA16816(acc[mt][nt], al[mt], bh[nt]);
            }
    }
}

#define GEMM_MAIN(AHI, ALO, BHI, BLO, LDB, BN)                                   \
    extern __shared__ char smem[];                                               \
    const uint32_t sbase = smem_u32(smem);                                       \
    const int tid  = threadIdx.x;                                                \
    const int lane = tid & 31;                                                   \
    const int w    = tid >> 5;                                                   \
    const int m0   = (w >> 1) << 5;                                              \
    const int n0   = (w & 1) << 6;                                               \
    float acc[2][8][4];                                                          \
    _Pragma("unroll")                                                            \
    for (int mt = 0; mt < 2; ++mt)                                               \
        _Pragma("unroll")                                                        \
        for (int nt = 0; nt < 8; ++nt)                                           \
            _Pragma("unroll")                                                    \
            for (int e = 0; e < 4; ++e) acc[mt][nt][e] = 0.f;                    \
    prefetch_slab(sbase, AHI, ALO, BHI, BLO, LDB, BN, 0, tid);                   \
    CP_COMMIT();                                                                 \
    for (int ks = 0; ks < NSLAB; ++ks) {                                         \
        if (ks + 1 < NSLAB) {                                                    \
            prefetch_slab(sbase + ((ks + 1) & 1) * STG_STRIDE,                   \
                          AHI, ALO, BHI, BLO, LDB, BN, (ks + 1) * 32, tid);      \
            CP_COMMIT();                                                         \
            CP_WAIT(1);                                                          \
        } else {                                                                 \
            CP_WAIT(0);                                                          \
        }                                                                        \
        __syncthreads();                                                         \
        compute_slab(smem + (ks & 1) * STG_STRIDE, m0, n0, lane, acc);           \
        __syncthreads();                                                         \
    }

// ---------------------------------------------------------------------------
// QKV GEMM: g_qkv[MTOK,1536] = tok[MTOKPAD,512] @ W_qkv[512,1536]
// ---------------------------------------------------------------------------
__global__ void __launch_bounds__(256) qkv_gemm(void)
{
    const int bm = blockIdx.y << 7;
    const int bn = blockIdx.x << 7;
    GEMM_MAIN(g_tok_hi + (size_t)bm * D, g_tok_lo + (size_t)bm * D,
              g_wq_hi, g_wq_lo, NQKV, bn)

    #pragma unroll
    for (int mt = 0; mt < 2; ++mt) {
        int r0 = bm + m0 + (mt << 4) + (lane >> 2);
        #pragma unroll
        for (int nt = 0; nt < 8; ++nt) {
            int c = bn + n0 + (nt << 3) + ((lane & 3) << 1);
            if (r0 < MTOK)
                *(float2*)(g_qkv + (size_t)r0 * NQKV + c) =
                    make_float2(acc[mt][nt][0], acc[mt][nt][1]);
            if (r0 + 8 < MTOK)
                *(float2*)(g_qkv + (size_t)(r0 + 8) * NQKV + c) =
                    make_float2(acc[mt][nt][2], acc[mt][nt][3]);
        }
    }
}

// ---------------------------------------------------------------------------
// Proj GEMM: (attn out)[32768,512] @ W_proj[512,512] + bias, fused scatter.
// ---------------------------------------------------------------------------
__device__ __forceinline__ void scatter_out(float* __restrict__ out, int r, int c, float v)
{
    int bs = r >> 5, t = r & 31, b = bs >> 8, s = bs & 255;
    if (t < 8) {
        out[((size_t)((((b << 3) + t) << 8) + s) << 9) + c] = v;
    } else if (t < 16) {
        out[OFF1 + ((size_t)((((b << 3) + (t - 8)) << 8) + s) << 9) + c] = v;
    } else if (t < 24) {
        atomicAdd(out + OFF2 + (((b << 3) + (t - 16)) << 9) + c, v * (1.f / 256.f));
    } else {
        atomicAdd(out + OFF3 + (((b << 3) + (t - 24)) << 9) + c, v * (1.f / 256.f));
    }
}

__global__ void __launch_bounds__(256) proj_gemm(
    const float* __restrict__ bias, float* __restrict__ out)
{
    const int bm = blockIdx.y << 7;
    const int bn = blockIdx.x << 7;
    GEMM_MAIN(g_o_hi + (size_t)bm * D, g_o_lo + (size_t)bm * D,
              g_wp_hi, g_wp_lo, D, bn)

    #pragma unroll
    for (int mt = 0; mt < 2; ++mt) {
        int r0 = bm + m0 + (mt << 4) + (lane >> 2);
        #pragma unroll
        for (int nt = 0; nt < 8; ++nt) {
            int c = bn + n0 + (nt << 3) + ((lane & 3) << 1);
            float b0 = bias[c], b1 = bias[c + 1];
            scatter_out(out, r0,     c,     acc[mt][nt][0] + b0);
            scatter_out(out, r0,     c + 1, acc[mt][nt][1] + b1);
            scatter_out(out, r0 + 8, c,     acc[mt][nt][2] + b0);
            scatter_out(out, r0 + 8, c + 1, acc[mt][nt][3] + b1);
        }
    }
}

// ---------------------------------------------------------------------------
// Attention: one block per (bs, head). 32x32 over hd=64, RoPE from table.
// Register-blocked (R6 scalar layout — measured best).
// ---------------------------------------------------------------------------
__global__ void __launch_bounds__(128) attn_kernel()
{
    __shared__ float Qs[32][65];
    __shared__ float Ks[32][65];
    __shared__ float Vs[32][65];
    __shared__ float Ss[32][33];

    const int tid = threadIdx.x;
    const int bh  = blockIdx.x;
    const int bs  = bh >> 3;
    const int h   = bh & 7;
    const int b   = bs >> 8;

    #pragma unroll
    for (int p = 0; p < 4; ++p) {
        int idx = tid + (p << 7);
        int t   = idx >> 4;
        int c4  = (idx & 15) << 2;
        int row = (t < 16) ? ((bs << 4) + t) : (MV + (b << 4) + (t - 16));
        const float* qp = g_qkv + (size_t)row * NQKV + (h << 6) + c4;
        float4 q = *(const float4*)(qp);
        float4 k = *(const float4*)(qp + 512);
        float4 v = *(const float4*)(qp + 1024);
        Qs[t][c4 + 0] = q.x; Qs[t][c4 + 1] = q.y; Qs[t][c4 + 2] = q.z; Qs[t][c4 + 3] = q.w;
        Ks[t][c4 + 0] = k.x; Ks[t][c4 + 1] = k.y; Ks[t][c4 + 2] = k.z; Ks[t][c4 + 3] = k.w;
        Vs[t][c4 + 0] = v.x; Vs[t][c4 + 1] = v.y; Vs[t][c4 + 2] = v.z; Vs[t][c4 + 3] = v.w;
    }
    __syncthreads();

    // RoPE in-place on Q,K (sin/cos from precomputed table, L2-resident)
    #pragma unroll
    for (int p = 0; p < 8; ++p) {
        int idx = tid + (p << 7);
        int t = idx >> 5;
        int j = idx & 31;
        float2 sc = g_rope[idx];
        float sn = sc.x, cs = sc.y;
        float q1 = Qs[t][j], q2 = Qs[t][j + 32];
        Qs[t][j]      = q1 * cs - q2 * sn;
        Qs[t][j + 32] = q2 * cs + q1 * sn;
        float k1 = Ks[t][j], k2 = Ks[t][j + 32];
        Ks[t][j]      = k1 * cs - k2 * sn;
        Ks[t][j + 32] = k2 * cs + k1 * sn;
    }
    __syncthreads();

    // S = (Q K^T) * scale: 2x4 register block per thread
    {
        const int r0 = (tid >> 3) << 1;     // 0,2,..,30
        const int c0 = (tid & 7) << 2;      // 0,4,..,28
        float s[2][4] = {{0.f,0.f,0.f,0.f},{0.f,0.f,0.f,0.f}};
        #pragma unroll
        for (int c = 0; c < 64; ++c) {
            float q0 = Qs[r0][c], q1 = Qs[r0 + 1][c];
            float k0 = Ks[c0][c], k1 = Ks[c0+1][c], k2 = Ks[c0+2][c], k3 = Ks[c0+3][c];
            s[0][0] += q0*k0; s[0][1] += q0*k1; s[0][2] += q0*k2; s[0][3] += q0*k3;
            s[1][0] += q1*k0; s[1][1] += q1*k1; s[1][2] += q1*k2; s[1][3] += q1*k3;
        }
        #pragma unroll
        for (int i = 0; i < 2; ++i)
            #pragma unroll
            for (int j = 0; j < 4; ++j)
                Ss[r0 + i][c0 + j] = s[i][j] * 0.125f;
    }
    __syncthreads();

    // Row softmax
    const int lane = tid & 31;
    const int w    = tid >> 5;
    #pragma unroll
    for (int rr = 0; rr < 8; ++rr) {
        int i = (w << 3) + rr;
        float val = Ss[i][lane];
        float m = val;
        #pragma unroll
        for (int o = 16; o > 0; o >>= 1) m = fmaxf(m, __shfl_xor_sync(0xffffffffu, m, o));
        float e = expf(val - m);
        float sum = e;
        #pragma unroll
        for (int o = 16; o > 0; o >>= 1) sum += __shfl_xor_sync(0xffffffffu, sum, o);
        Ss[i][lane] = e / sum;
    }
    __syncthreads();

    // O = P @ V: 4x4 register block per thread -> bf16 hi/lo
    {
        const int r0 = (tid >> 4) << 2;     // 0,4,..,28
        const int c0 = (tid & 15) << 2;     // 0,4,..,60
        float o[4][4];
        #pragma unroll
        for (int i = 0; i < 4; ++i)
            #pragma unroll
            for (int j = 0; j < 4; ++j) o[i][j] = 0.f;
        #pragma unroll
        for (int j = 0; j < 32; ++j) {
            float v0 = Vs[j][c0], v1 = Vs[j][c0+1], v2 = Vs[j][c0+2], v3 = Vs[j][c0+3];
            float s0 = Ss[r0][j], s1 = Ss[r0+1][j], s2 = Ss[r0+2][j], s3 = Ss[r0+3][j];
            o[0][0] += s0*v0; o[0][1] += s0*v1; o[0][2] += s0*v2; o[0][3] += s0*v3;
            o[1][0] += s1*v0; o[1][1] += s1*v1; o[1][2] += s1*v2; o[1][3] += s1*v3;
            o[2][0] += s2*v0; o[2][1] += s2*v1; o[2][2] += s2*v2; o[2][3] += s2*v3;
            o[3][0] += s3*v0; o[3][1] += s3*v1; o[3][2] += s3*v2; o[3][3] += s3*v3;
        }
        #pragma unroll
        for (int i = 0; i < 4; ++i) {
            __nv_bfloat16 h0,l0,h1,l1,h2,l2,h3,l3;
            cvt_hilo(o[i][0], h0, l0); cvt_hilo(o[i][1], h1, l1);
            cvt_hilo(o[i][2], h2, l2); cvt_hilo(o[i][3], h3, l3);
            size_t off = (size_t)((bs << 5) + r0 + i) * D + (h << 6) + c0;
            *(__nv_bfloat162*)(g_o_hi + off)     = __nv_bfloat162(h0, h1);
            *(__nv_bfloat162*)(g_o_hi + off + 2) = __nv_bfloat162(h2, h3);
            *(__nv_bfloat162*)(g_o_lo + off)     = __nv_bfloat162(l0, l1);
            *(__nv_bfloat162*)(g_o_lo + off + 2) = __nv_bfloat162(l2, l3);
        }
    }
}

// ---------------------------------------------------------------------------
__global__ void zero_tail_kernel(float* __restrict__ out)
{
    int i = blockIdx.x * 256 + threadIdx.x;
    if (i < 32768) out[OFF2 + i] = 0.f;
}

// ---------------------------------------------------------------------------
extern "C" void kernel_launch(void* const* d_in, const int* in_sizes, int n_in,
                              void* d_out, int out_size)
{
    const float* v_p    = (const float*)d_in[0];
    const float* v_f    = (const float*)d_in[1];
    const float* a_p    = (const float*)d_in[2];
    const float* a_f    = (const float*)d_in[3];
    const float* W_qkv  = (const float*)d_in[4];
    const float* W_proj = (const float*)d_in[5];
    const float* b_proj = (const float*)d_in[6];
    float* out = (float*)d_out;

    cudaFuncSetAttribute(qkv_gemm,  cudaFuncAttributeMaxDynamicSharedMemorySize, SMEM_BYTES);
    cudaFuncSetAttribute(proj_gemm, cudaFuncAttributeMaxDynamicSharedMemorySize, SMEM_BYTES);

    rope_table_kernel<<<4, 256>>>();
    conv_weights<<<1024, 256>>>(W_qkv, W_proj);
    conv_tokens<<<8224, 256>>>(v_p, v_f, a_p, a_f);

    qkv_gemm<<<dim3(12, 129), 256, SMEM_BYTES>>>();

    attn_kernel<<<8192, 128>>>();

    zero_tail_kernel<<<128, 256>>>(out);
    proj_gemm<<<dim3(4, 256), 256, SMEM_BYTES>>>(b_proj, out);
}

// round 11
// speedup vs baseline: 1.1265x; 1.0116x over previous
#include <cuda_runtime.h>
#include <cuda_bf16.h>
#include <stdint.h>
#include <math.h>

// Problem constants
#define D       512
#define NQKV    1536
#define MV      16384       // unique v-token rows (B*S*16)
#define MTOK    16448       // + 64 a-token rows
#define MTOKPAD 16512       // padded to tile multiple
#define NROWS   32768

// Output layout offsets (floats)
#define OFF1    4194304     // vf_o
#define OFF2    8388608     // ap_o
#define OFF3    8404992     // af_o

// Scratch
__device__ __nv_bfloat16 g_tok_hi[(size_t)MTOKPAD * D];
__device__ __nv_bfloat16 g_tok_lo[(size_t)MTOKPAD * D];
__device__ __nv_bfloat16 g_wq_hi[(size_t)D * NQKV];
__device__ __nv_bfloat16 g_wq_lo[(size_t)D * NQKV];
__device__ __nv_bfloat16 g_wp_hi[(size_t)D * D];
__device__ __nv_bfloat16 g_wp_lo[(size_t)D * D];
__device__ float         g_qkv[(size_t)MTOK * NQKV];
__device__ __nv_bfloat16 g_o_hi[(size_t)NROWS * D];
__device__ __nv_bfloat16 g_o_lo[(size_t)NROWS * D];
__device__ float2        g_rope[1024];   // (sin, cos) for t*32+j

// ---------------------------------------------------------------------------
__device__ __forceinline__ uint32_t smem_u32(const void* p) {
    return (uint32_t)__cvta_generic_to_shared(p);
}

#define LDSM_X4(r0,r1,r2,r3,addr) \
    asm volatile("ldmatrix.sync.aligned.m8n8.x4.shared.b16 {%0,%1,%2,%3}, [%4];" \
        : "=r"(r0),"=r"(r1),"=r"(r2),"=r"(r3) : "r"(addr))

#define LDSM_X4_T(r0,r1,r2,r3,addr) \
    asm volatile("ldmatrix.sync.aligned.m8n8.x4.trans.shared.b16 {%0,%1,%2,%3}, [%4];" \
        : "=r"(r0),"=r"(r1),"=r"(r2),"=r"(r3) : "r"(addr))

#define MMA16816(d, a, b) \
    asm volatile("mma.sync.aligned.m16n8k16.row.col.f32.bf16.bf16.f32 " \
        "{%0,%1,%2,%3},{%4,%5,%6,%7},{%8,%9},{%0,%1,%2,%3};" \
        : "+f"(d[0]),"+f"(d[1]),"+f"(d[2]),"+f"(d[3]) \
        : "r"(a[0]),"r"(a[1]),"r"(a[2]),"r"(a[3]),"r"(b[0]),"r"(b[1]))

#define CP16(dst, src) \
    asm volatile("cp.async.cg.shared.global [%0], [%1], 16;" :: "r"(dst), "l"(src))
#define CP_COMMIT() asm volatile("cp.async.commit_group;")
#define CP_WAIT(n)  asm volatile("cp.async.wait_group %0;" :: "n"(n))

__device__ __forceinline__ void cvt_hilo(float x, __nv_bfloat16& h, __nv_bfloat16& l) {
    h = __float2bfloat16(x);
    l = __float2bfloat16(x - __bfloat162float(h));
}

// Token row gather: mode 0 = v-tokens, mode 1 = a-tokens
__device__ __forceinline__ const float* token_ptr(int r, int mode,
    const float* __restrict__ p0, const float* __restrict__ p1)
{
    if (mode == 0) {
        int b = r >> 12;
        int rem = r & 4095;
        int s = rem >> 4;
        int t = rem & 15;
        if (t < 8)  return p0 + ((size_t)((((b << 3) + t) << 8) + s) << 9);
        else        return p1 + ((size_t)((((b << 3) + (t - 8)) << 8) + s) << 9);
    } else {
        int b = r >> 4;
        int t = r & 15;
        if (t < 8)  return p0 + ((size_t)((b << 3) + t) << 9);
        else        return p1 + ((size_t)((b << 3) + (t - 8)) << 9);
    }
}

// ---------------------------------------------------------------------------
// Pre-conversion kernels
// ---------------------------------------------------------------------------
__global__ void __launch_bounds__(256) conv_tokens(
    const float* __restrict__ v_p, const float* __restrict__ v_f,
    const float* __restrict__ a_p, const float* __restrict__ a_f)
{
    int idx = blockIdx.x * 256 + threadIdx.x;    // one float4 per thread
    int row = idx >> 7;
    int c4  = (idx & 127) << 2;
    if (row >= MTOK) return;
    const float* src = (row < MV) ? token_ptr(row, 0, v_p, v_f)
                                  : token_ptr(row - MV, 1, a_p, a_f);
    float4 v = *(const float4*)(src + c4);
    __nv_bfloat16 h[4], l[4];
    cvt_hilo(v.x, h[0], l[0]); cvt_hilo(v.y, h[1], l[1]);
    cvt_hilo(v.z, h[2], l[2]); cvt_hilo(v.w, h[3], l[3]);
    size_t off = (size_t)row * D + c4;
    *(__nv_bfloat162*)(g_tok_hi + off)     = __nv_bfloat162(h[0], h[1]);
    *(__nv_bfloat162*)(g_tok_hi + off + 2) = __nv_bfloat162(h[2], h[3]);
    *(__nv_bfloat162*)(g_tok_lo + off)     = __nv_bfloat162(l[0], l[1]);
    *(__nv_bfloat162*)(g_tok_lo + off + 2) = __nv_bfloat162(l[2], l[3]);
}

__global__ void __launch_bounds__(256) conv_weights(
    const float* __restrict__ Wq, const float* __restrict__ Wp)
{
    int idx = blockIdx.x * 256 + threadIdx.x;    // one float4 per thread
    const int NQ4 = (D * NQKV) / 4;              // 196608
    const float* src;
    __nv_bfloat16 *dh, *dl;
    size_t off;
    if (idx < NQ4)      { src = Wq; dh = g_wq_hi; dl = g_wq_lo; off = (size_t)idx << 2; }
    else                { idx -= NQ4;
                          if (idx >= (D * D) / 4) return;
                          src = Wp; dh = g_wp_hi; dl = g_wp_lo; off = (size_t)idx << 2; }
    float4 v = *(const float4*)(src + off);
    __nv_bfloat16 h[4], l[4];
    cvt_hilo(v.x, h[0], l[0]); cvt_hilo(v.y, h[1], l[1]);
    cvt_hilo(v.z, h[2], l[2]); cvt_hilo(v.w, h[3], l[3]);
    *(__nv_bfloat162*)(dh + off)     = __nv_bfloat162(h[0], h[1]);
    *(__nv_bfloat162*)(dh + off + 2) = __nv_bfloat162(h[2], h[3]);
    *(__nv_bfloat162*)(dl + off)     = __nv_bfloat162(l[0], l[1]);
    *(__nv_bfloat162*)(dl + off + 2) = __nv_bfloat162(l[2], l[3]);
}

// RoPE sin/cos table: entry t*32+j = (sin, cos) of t * 10000^(-j/32)
__global__ void rope_table_kernel(void)
{
    int idx = threadIdx.x + blockIdx.x * 256;
    if (idx >= 1024) return;
    int t = idx >> 5;
    int j = idx & 31;
    float inv = exp2f(-0.41524101186091903f * (float)j);
    float ang = (float)t * inv;
    float sn, cs;
    sincosf(ang, &sn, &cs);
    g_rope[idx] = make_float2(sn, cs);
}

// ---------------------------------------------------------------------------
// Pipelined bf16x3 GEMM: 128x128 tile, BK=32, 2-stage cp.async, 256 threads.
// Stage layout (bytes): Ahi[128][40], Alo, Bhi[32][136], Blo
// ---------------------------------------------------------------------------
#define STG_A_HI   0
#define STG_A_LO   10240
#define STG_B_HI   20480
#define STG_B_LO   29184
#define STG_STRIDE 37888
#define SMEM_BYTES (2 * STG_STRIDE)
#define NSLAB      16

__device__ __forceinline__ void prefetch_slab(
    uint32_t stg,
    const __nv_bfloat16* __restrict__ Ahi, const __nv_bfloat16* __restrict__ Alo,
    const __nv_bfloat16* __restrict__ Bhi, const __nv_bfloat16* __restrict__ Blo,
    int ldb, int bn, int k0, int tid)
{
    #pragma unroll
    for (int t = 0; t < 2; ++t) {
        int q  = tid + (t << 8);              // 0..511
        int r  = q >> 2, kc = (q & 3) << 3;   // A: 128 rows x 4 chunks
        uint32_t ao = (uint32_t)(r * 80 + (kc << 1));
        size_t asrc = (size_t)r * D + k0 + kc;
        CP16(stg + STG_A_HI + ao, Ahi + asrc);
        CP16(stg + STG_A_LO + ao, Alo + asrc);
        int br = q >> 4, nc = (q & 15) << 3;  // B: 32 rows x 16 chunks
        uint32_t bo = (uint32_t)(br * 272 + (nc << 1));
        size_t bsrc = (size_t)(k0 + br) * ldb + bn + nc;
        CP16(stg + STG_B_HI + bo, Bhi + bsrc);
        CP16(stg + STG_B_LO + bo, Blo + bsrc);
    }
}

__device__ __forceinline__ void compute_slab(
    char* stg, int m0, int n0, int lane, float (&acc)[2][8][4])
{
    uint32_t ah[2][4], al[2][4], bh[8][2], bl[8][2];
    #pragma unroll
    for (int ks = 0; ks < 2; ++ks) {
        const int k0   = ks << 4;
        const int arow = lane & 15;
        const int acol = k0 + ((lane >> 4) << 3);
        #pragma unroll
        for (int mt = 0; mt < 2; ++mt) {
            uint32_t ad = smem_u32(stg + STG_A_HI + (m0 + (mt << 4) + arow) * 80 + acol * 2);
            LDSM_X4(ah[mt][0], ah[mt][1], ah[mt][2], ah[mt][3], ad);
            uint32_t ad2 = smem_u32(stg + STG_A_LO + (m0 + (mt << 4) + arow) * 80 + acol * 2);
            LDSM_X4(al[mt][0], al[mt][1], al[mt][2], al[mt][3], ad2);
        }
        #pragma unroll
        for (int p = 0; p < 4; ++p) {
            const int ncol = n0 + (p << 4) + ((lane >> 4) << 3);
            uint32_t bd = smem_u32(stg + STG_B_HI + (k0 + (lane & 15)) * 272 + ncol * 2);
            LDSM_X4_T(bh[2*p][0], bh[2*p][1], bh[2*p+1][0], bh[2*p+1][1], bd);
            uint32_t bd2 = smem_u32(stg + STG_B_LO + (k0 + (lane & 15)) * 272 + ncol * 2);
            LDSM_X4_T(bl[2*p][0], bl[2*p][1], bl[2*p+1][0], bl[2*p+1][1], bd2);
        }
        #pragma unroll
        for (int mt = 0; mt < 2; ++mt)
            #pragma unroll
            for (int nt = 0; nt < 8; ++nt) {
                MMA16816(acc[mt][nt], ah[mt], bh[nt]);
                MMA16816(acc[mt][nt], ah[mt], bl[nt]);
                MMA16816(acc[mt][nt], al[mt], bh[nt]);
            }
    }
}

#define GEMM_MAIN(AHI, ALO, BHI, BLO, LDB, BN)                                   \
    extern __shared__ char smem[];                                               \
    const uint32_t sbase = smem_u32(smem);                                       \
    const int tid  = threadIdx.x;                                                \
    const int lane = tid & 31;                                                   \
    const int w    = tid >> 5;                                                   \
    const int m0   = (w >> 1) << 5;                                              \
    const int n0   = (w & 1) << 6;                                               \
    float acc[2][8][4];                                                          \
    _Pragma("unroll")                                                            \
    for (int mt = 0; mt < 2; ++mt)                                               \
        _Pragma("unroll")                                                        \
        for (int nt = 0; nt < 8; ++nt)                                           \
            _Pragma("unroll")                                                    \
            for (int e = 0; e < 4; ++e) acc[mt][nt][e] = 0.f;                    \
    prefetch_slab(sbase, AHI, ALO, BHI, BLO, LDB, BN, 0, tid);                   \
    CP_COMMIT();                                                                 \
    for (int ks = 0; ks < NSLAB; ++ks) {                                         \
        if (ks + 1 < NSLAB) {                                                    \
            prefetch_slab(sbase + ((ks + 1) & 1) * STG_STRIDE,                   \
                          AHI, ALO, BHI, BLO, LDB, BN, (ks + 1) * 32, tid);      \
            CP_COMMIT();                                                         \
            CP_WAIT(1);                                                          \
        } else {                                                                 \
            CP_WAIT(0);                                                          \
        }                                                                        \
        __syncthreads();                                                         \
        compute_slab(smem + (ks & 1) * STG_STRIDE, m0, n0, lane, acc);           \
        __syncthreads();                                                         \
    }

// ---------------------------------------------------------------------------
// QKV GEMM: g_qkv[MTOK,1536] = tok[MTOKPAD,512] @ W_qkv[512,1536]
// ---------------------------------------------------------------------------
__global__ void __launch_bounds__(256) qkv_gemm(void)
{
    const int bm = blockIdx.y << 7;
    const int bn = blockIdx.x << 7;
    GEMM_MAIN(g_tok_hi + (size_t)bm * D, g_tok_lo + (size_t)bm * D,
              g_wq_hi, g_wq_lo, NQKV, bn)

    #pragma unroll
    for (int mt = 0; mt < 2; ++mt) {
        int r0 = bm + m0 + (mt << 4) + (lane >> 2);
        #pragma unroll
        for (int nt = 0; nt < 8; ++nt) {
            int c = bn + n0 + (nt << 3) + ((lane & 3) << 1);
            if (r0 < MTOK)
                *(float2*)(g_qkv + (size_t)r0 * NQKV + c) =
                    make_float2(acc[mt][nt][0], acc[mt][nt][1]);
            if (r0 + 8 < MTOK)
                *(float2*)(g_qkv + (size_t)(r0 + 8) * NQKV + c) =
                    make_float2(acc[mt][nt][2], acc[mt][nt][3]);
        }
    }
}

// ---------------------------------------------------------------------------
// Proj GEMM: (attn out)[32768,512] @ W_proj[512,512] + bias, fused scatter.
// ---------------------------------------------------------------------------
__device__ __forceinline__ void scatter_out(float* __restrict__ out, int r, int c, float v)
{
    int bs = r >> 5, t = r & 31, b = bs >> 8, s = bs & 255;
    if (t < 8) {
        out[((size_t)((((b << 3) + t) << 8) + s) << 9) + c] = v;
    } else if (t < 16) {
        out[OFF1 + ((size_t)((((b << 3) + (t - 8)) << 8) + s) << 9) + c] = v;
    } else if (t < 24) {
        atomicAdd(out + OFF2 + (((b << 3) + (t - 16)) << 9) + c, v * (1.f / 256.f));
    } else {
        atomicAdd(out + OFF3 + (((b << 3) + (t - 24)) << 9) + c, v * (1.f / 256.f));
    }
}

__global__ void __launch_bounds__(256) proj_gemm(
    const float* __restrict__ bias, float* __restrict__ out)
{
    const int bm = blockIdx.y << 7;
    const int bn = blockIdx.x << 7;
    GEMM_MAIN(g_o_hi + (size_t)bm * D, g_o_lo + (size_t)bm * D,
              g_wp_hi, g_wp_lo, D, bn)

    #pragma unroll
    for (int mt = 0; mt < 2; ++mt) {
        int r0 = bm + m0 + (mt << 4) + (lane >> 2);
        #pragma unroll
        for (int nt = 0; nt < 8; ++nt) {
            int c = bn + n0 + (nt << 3) + ((lane & 3) << 1);
            float b0 = bias[c], b1 = bias[c + 1];
            scatter_out(out, r0,     c,     acc[mt][nt][0] + b0);
            scatter_out(out, r0,     c + 1, acc[mt][nt][1] + b1);
            scatter_out(out, r0 + 8, c,     acc[mt][nt][2] + b0);
            scatter_out(out, r0 + 8, c + 1, acc[mt][nt][3] + b1);
        }
    }
}

// ---------------------------------------------------------------------------
// Attention (tensor-core): one block per (bs, head), 128 threads (4 warps).
// S = QK^T and O = PV via bf16x3 mma.sync; softmax in fp32.
// All bf16 tile strides are multiples of 8 elements (16B) for ldmatrix.
// Smem layout (bytes):
//   Qs  [32][65] f32   @ 0       (8320)
//   Ks  [32][65] f32   @ 8320    (8320)
//   QH/QL  [32][72] bf16 @ 16640 / 21248  (4608 each, 144B rows)
//   KTH/KTL[64][40] bf16 @ 25856 / 30976  (5120 each, 80B rows, K transposed)
//   VH/VL  [32][72] bf16 @ 36096 / 40704  (4608 each, 144B rows)
//   PH/PL  [32][40] bf16 @ 45312 / 47872  (2560 each, 80B rows)
//   Ss  [32][33] f32   @ 50432   (4224)    total 54656
// ---------------------------------------------------------------------------
#define A_QSF 0
#define A_KSF 8320
#define A_QH  16640
#define A_QL  21248
#define A_KTH 25856
#define A_KTL 30976
#define A_VH  36096
#define A_VL  40704
#define A_PH  45312
#define A_PL  47872
#define A_SS  50432
#define ATT_SMEM 54656

__global__ void __launch_bounds__(128) attn_kernel()
{
    extern __shared__ char asm_[];
    float* Qs = (float*)(asm_ + A_QSF);                 // [32][65]
    float* Ks = (float*)(asm_ + A_KSF);                 // [32][65]
    __nv_bfloat16* QH = (__nv_bfloat16*)(asm_ + A_QH);  // [32][72]
    __nv_bfloat16* QL = (__nv_bfloat16*)(asm_ + A_QL);
    __nv_bfloat16* KTH = (__nv_bfloat16*)(asm_ + A_KTH);// [64][40]
    __nv_bfloat16* KTL = (__nv_bfloat16*)(asm_ + A_KTL);
    __nv_bfloat16* VH = (__nv_bfloat16*)(asm_ + A_VH);  // [32][72]
    __nv_bfloat16* VL = (__nv_bfloat16*)(asm_ + A_VL);
    __nv_bfloat16* PH = (__nv_bfloat16*)(asm_ + A_PH);  // [32][40]
    __nv_bfloat16* PL = (__nv_bfloat16*)(asm_ + A_PL);
    float* Ss = (float*)(asm_ + A_SS);                  // [32][33]

    const int tid  = threadIdx.x;
    const int lane = tid & 31;
    const int w    = tid >> 5;
    const int bh   = blockIdx.x;
    const int bs   = bh >> 3;
    const int h    = bh & 7;
    const int b    = bs >> 8;

    // Phase 1: load Q,K (fp32 smem) and V (convert to bf16 hi/lo directly)
    #pragma unroll
    for (int p = 0; p < 4; ++p) {
        int idx = tid + (p << 7);
        int t   = idx >> 4;
        int c4  = (idx & 15) << 2;
        int row = (t < 16) ? ((bs << 4) + t) : (MV + (b << 4) + (t - 16));
        const float* qp = g_qkv + (size_t)row * NQKV + (h << 6) + c4;
        float4 q = *(const float4*)(qp);
        float4 k = *(const float4*)(qp + 512);
        float4 v = *(const float4*)(qp + 1024);
        Qs[t*65 + c4 + 0] = q.x; Qs[t*65 + c4 + 1] = q.y;
        Qs[t*65 + c4 + 2] = q.z; Qs[t*65 + c4 + 3] = q.w;
        Ks[t*65 + c4 + 0] = k.x; Ks[t*65 + c4 + 1] = k.y;
        Ks[t*65 + c4 + 2] = k.z; Ks[t*65 + c4 + 3] = k.w;
        __nv_bfloat16 h0,l0,h1,l1,h2,l2,h3,l3;
        cvt_hilo(v.x, h0, l0); cvt_hilo(v.y, h1, l1);
        cvt_hilo(v.z, h2, l2); cvt_hilo(v.w, h3, l3);
        *(__nv_bfloat162*)(VH + t*72 + c4)     = __nv_bfloat162(h0, h1);
        *(__nv_bfloat162*)(VH + t*72 + c4 + 2) = __nv_bfloat162(h2, h3);
        *(__nv_bfloat162*)(VL + t*72 + c4)     = __nv_bfloat162(l0, l1);
        *(__nv_bfloat162*)(VL + t*72 + c4 + 2) = __nv_bfloat162(l2, l3);
    }
    __syncthreads();

    // Phase 2: RoPE in-place on Qs, Ks (table)
    #pragma unroll
    for (int p = 0; p < 8; ++p) {
        int idx = tid + (p << 7);
        int t = idx >> 5;
        int j = idx & 31;
        float2 sc = g_rope[idx];
        float sn = sc.x, cs = sc.y;
        float q1 = Qs[t*65 + j], q2 = Qs[t*65 + j + 32];
        Qs[t*65 + j]      = q1 * cs - q2 * sn;
        Qs[t*65 + j + 32] = q2 * cs + q1 * sn;
        float k1 = Ks[t*65 + j], k2 = Ks[t*65 + j + 32];
        Ks[t*65 + j]      = k1 * cs - k2 * sn;
        Ks[t*65 + j + 32] = k2 * cs + k1 * sn;
    }
    __syncthreads();

    // Phase 3: convert Q -> QH/QL (row-major) and K -> KTH/KTL (transposed)
    if (tid < 64) {
        int j = tid;                      // k-dim column 0..63
        #pragma unroll
        for (int t = 0; t < 32; ++t) {
            __nv_bfloat16 hh, ll;
            cvt_hilo(Ks[t*65 + j], hh, ll);
            KTH[j*40 + t] = hh;
            KTL[j*40 + t] = ll;
        }
    } else {
        int jj = tid - 64;
        int r  = jj >> 1;
        int cb = (jj & 1) << 5;           // 0 or 32
        #pragma unroll
        for (int c = 0; c < 32; c += 2) {
            __nv_bfloat16 h0, l0, h1, l1;
            cvt_hilo(Qs[r*65 + cb + c],     h0, l0);
            cvt_hilo(Qs[r*65 + cb + c + 1], h1, l1);
            *(__nv_bfloat162*)(QH + r*72 + cb + c) = __nv_bfloat162(h0, h1);
            *(__nv_bfloat162*)(QL + r*72 + cb + c) = __nv_bfloat162(l0, l1);
        }
    }
    __syncthreads();

    // Phase 4: S = QK^T * scale via MMA. Warp w: m0=(w&1)*16, n0=(w>>1)*16.
    {
        const int m0 = (w & 1) << 4;
        const int n0 = (w >> 1) << 4;
        float sacc[2][4] = {{0.f,0.f,0.f,0.f},{0.f,0.f,0.f,0.f}};
        uint32_t ah[4], al[4], bh[2][2], bl[2][2];
        #pragma unroll
        for (int kc = 0; kc < 4; ++kc) {
            const int k0 = kc << 4;
            const int arow = m0 + (lane & 15);
            const int acol = k0 + ((lane >> 4) << 3);
            LDSM_X4(ah[0], ah[1], ah[2], ah[3], smem_u32(QH + arow*72 + acol));
            LDSM_X4(al[0], al[1], al[2], al[3], smem_u32(QL + arow*72 + acol));
            const int brow = k0 + (lane & 15);
            const int bcol = n0 + ((lane >> 4) << 3);
            LDSM_X4_T(bh[0][0], bh[0][1], bh[1][0], bh[1][1], smem_u32(KTH + brow*40 + bcol));
            LDSM_X4_T(bl[0][0], bl[0][1], bl[1][0], bl[1][1], smem_u32(KTL + brow*40 + bcol));
            #pragma unroll
            for (int nt = 0; nt < 2; ++nt) {
                MMA16816(sacc[nt], ah, bh[nt]);
                MMA16816(sacc[nt], ah, bl[nt]);
                MMA16816(sacc[nt], al, bh[nt]);
            }
        }
        const int r0 = m0 + (lane >> 2);
        #pragma unroll
        for (int nt = 0; nt < 2; ++nt) {
            int c = n0 + (nt << 3) + ((lane & 3) << 1);
            Ss[r0*33 + c]       = sacc[nt][0] * 0.125f;
            Ss[r0*33 + c + 1]   = sacc[nt][1] * 0.125f;
            Ss[(r0+8)*33 + c]     = sacc[nt][2] * 0.125f;
            Ss[(r0+8)*33 + c + 1] = sacc[nt][3] * 0.125f;
        }
    }
    __syncthreads();

    // Phase 5: row softmax; emit P as bf16 hi/lo directly
    #pragma unroll
    for (int rr = 0; rr < 8; ++rr) {
        int i = (w << 3) + rr;
        float val = Ss[i*33 + lane];
        float m = val;
        #pragma unroll
        for (int o = 16; o > 0; o >>= 1) m = fmaxf(m, __shfl_xor_sync(0xffffffffu, m, o));
        float e = expf(val - m);
        float sum = e;
        #pragma unroll
        for (int o = 16; o > 0; o >>= 1) sum += __shfl_xor_sync(0xffffffffu, sum, o);
        float pv = e / sum;
        __nv_bfloat16 hh, ll;
        cvt_hilo(pv, hh, ll);
        PH[i*40 + lane] = hh;
        PL[i*40 + lane] = ll;
    }
    __syncthreads();

    // Phase 6: O = P @ V via MMA. Warp w: m0=(w&1)*16, n0=(w>>1)*32.
    {
        const int m0 = (w & 1) << 4;
        const int n0 = (w >> 1) << 5;
        float oacc[4][4];
        #pragma unroll
        for (int nt = 0; nt < 4; ++nt)
            #pragma unroll
            for (int e = 0; e < 4; ++e) oacc[nt][e] = 0.f;
        uint32_t ah[4], al[4], bh[4][2], bl[4][2];
        #pragma unroll
        for (int kc = 0; kc < 2; ++kc) {
            const int k0 = kc << 4;
            const int arow = m0 + (lane & 15);
            const int acol = k0 + ((lane >> 4) << 3);
            LDSM_X4(ah[0], ah[1], ah[2], ah[3], smem_u32(PH + arow*40 + acol));
            LDSM_X4(al[0], al[1], al[2], al[3], smem_u32(PL + arow*40 + acol));
            #pragma unroll
            for (int p = 0; p < 2; ++p) {
                const int brow = k0 + (lane & 15);
                const int bcol = n0 + (p << 4) + ((lane >> 4) << 3);
                LDSM_X4_T(bh[2*p][0], bh[2*p][1], bh[2*p+1][0], bh[2*p+1][1],
                          smem_u32(VH + brow*72 + bcol));
                LDSM_X4_T(bl[2*p][0], bl[2*p][1], bl[2*p+1][0], bl[2*p+1][1],
                          smem_u32(VL + brow*72 + bcol));
            }
            #pragma unroll
            for (int nt = 0; nt < 4; ++nt) {
                MMA16816(oacc[nt], ah, bh[nt]);
                MMA16816(oacc[nt], ah, bl[nt]);
                MMA16816(oacc[nt], al, bh[nt]);
            }
        }
        // Epilogue: cvt + store bf16 hi/lo
        const int r0 = m0 + (lane >> 2);
        #pragma unroll
        for (int nt = 0; nt < 4; ++nt) {
            int c = n0 + (nt << 3) + ((lane & 3) << 1);
            size_t o0 = (size_t)((bs << 5) + r0) * D + (h << 6) + c;
            size_t o1 = (size_t)((bs << 5) + r0 + 8) * D + (h << 6) + c;
            __nv_bfloat16 h0,l0,h1,l1,h2,l2,h3,l3;
            cvt_hilo(oacc[nt][0], h0, l0); cvt_hilo(oacc[nt][1], h1, l1);
            cvt_hilo(oacc[nt][2], h2, l2); cvt_hilo(oacc[nt][3], h3, l3);
            *(__nv_bfloat162*)(g_o_hi + o0) = __nv_bfloat162(h0, h1);
            *(__nv_bfloat162*)(g_o_lo + o0) = __nv_bfloat162(l0, l1);
            *(__nv_bfloat162*)(g_o_hi + o1) = __nv_bfloat162(h2, h3);
            *(__nv_bfloat162*)(g_o_lo + o1) = __nv_bfloat162(l2, l3);
        }
    }
}

// ---------------------------------------------------------------------------
__global__ void zero_tail_kernel(float* __restrict__ out)
{
    int i = blockIdx.x * 256 + threadIdx.x;
    if (i < 32768) out[OFF2 + i] = 0.f;
}

// ---------------------------------------------------------------------------
extern "C" void kernel_launch(void* const* d_in, const int* in_sizes, int n_in,
                              void* d_out, int out_size)
{
    const float* v_p    = (const float*)d_in[0];
    const float* v_f    = (const float*)d_in[1];
    const float* a_p    = (const float*)d_in[2];
    const float* a_f    = (const float*)d_in[3];
    const float* W_qkv  = (const float*)d_in[4];
    const float* W_proj = (const float*)d_in[5];
    const float* b_proj = (const float*)d_in[6];
    float* out = (float*)d_out;

    cudaFuncSetAttribute(qkv_gemm,  cudaFuncAttributeMaxDynamicSharedMemorySize, SMEM_BYTES);
    cudaFuncSetAttribute(proj_gemm, cudaFuncAttributeMaxDynamicSharedMemorySize, SMEM_BYTES);
    cudaFuncSetAttribute(attn_kernel, cudaFuncAttributeMaxDynamicSharedMemorySize, ATT_SMEM);

    rope_table_kernel<<<4, 256>>>();
    conv_weights<<<1024, 256>>>(W_qkv, W_proj);
    conv_tokens<<<8224, 256>>>(v_p, v_f, a_p, a_f);

    qkv_gemm<<<dim3(12, 129), 256, SMEM_BYTES>>>();

    attn_kernel<<<8192, 128, ATT_SMEM>>>();

    zero_tail_kernel<<<128, 256>>>(out);
    proj_gemm<<<dim3(4, 256), 256, SMEM_BYTES>>>(b_proj, out);
}

// round 12
// speedup vs baseline: 1.1577x; 1.0277x over previous
#include <cuda_runtime.h>
#include <cuda_bf16.h>
#include <stdint.h>
#include <math.h>

// Problem constants
#define D       512
#define NQKV    1536
#define MV      16384       // unique v-token rows (B*S*16)
#define MTOK    16448       // + 64 a-token rows
#define MTOKPAD 16512       // padded to tile multiple
#define NROWS   32768

// Output layout offsets (floats)
#define OFF1    4194304     // vf_o
#define OFF2    8388608     // ap_o
#define OFF3    8404992     // af_o

// Scratch
__device__ __nv_bfloat16 g_tok_hi[(size_t)MTOKPAD * D];
__device__ __nv_bfloat16 g_tok_lo[(size_t)MTOKPAD * D];
__device__ __nv_bfloat16 g_wq_hi[(size_t)D * NQKV];
__device__ __nv_bfloat16 g_wq_lo[(size_t)D * NQKV];
__device__ __nv_bfloat16 g_wp_hi[(size_t)D * D];
__device__ __nv_bfloat16 g_wp_lo[(size_t)D * D];
__device__ float         g_qkv[(size_t)MTOK * NQKV];
__device__ __nv_bfloat16 g_o_hi[(size_t)NROWS * D];
__device__ __nv_bfloat16 g_o_lo[(size_t)NROWS * D];
__device__ float2        g_rope[1024];   // (sin, cos) for t*32+j

// ---------------------------------------------------------------------------
__device__ __forceinline__ uint32_t smem_u32(const void* p) {
    return (uint32_t)__cvta_generic_to_shared(p);
}

#define LDSM_X4(r0,r1,r2,r3,addr) \
    asm volatile("ldmatrix.sync.aligned.m8n8.x4.shared.b16 {%0,%1,%2,%3}, [%4];" \
        : "=r"(r0),"=r"(r1),"=r"(r2),"=r"(r3) : "r"(addr))

#define LDSM_X4_T(r0,r1,r2,r3,addr) \
    asm volatile("ldmatrix.sync.aligned.m8n8.x4.trans.shared.b16 {%0,%1,%2,%3}, [%4];" \
        : "=r"(r0),"=r"(r1),"=r"(r2),"=r"(r3) : "r"(addr))

#define MMA16816(d, a, b) \
    asm volatile("mma.sync.aligned.m16n8k16.row.col.f32.bf16.bf16.f32 " \
        "{%0,%1,%2,%3},{%4,%5,%6,%7},{%8,%9},{%0,%1,%2,%3};" \
        : "+f"(d[0]),"+f"(d[1]),"+f"(d[2]),"+f"(d[3]) \
        : "r"(a[0]),"r"(a[1]),"r"(a[2]),"r"(a[3]),"r"(b[0]),"r"(b[1]))

#define CP16(dst, src) \
    asm volatile("cp.async.cg.shared.global [%0], [%1], 16;" :: "r"(dst), "l"(src))
#define CP_COMMIT() asm volatile("cp.async.commit_group;")
#define CP_WAIT(n)  asm volatile("cp.async.wait_group %0;" :: "n"(n))

__device__ __forceinline__ void cvt_hilo(float x, __nv_bfloat16& h, __nv_bfloat16& l) {
    h = __float2bfloat16(x);
    l = __float2bfloat16(x - __bfloat162float(h));
}

// Token row gather: mode 0 = v-tokens, mode 1 = a-tokens
__device__ __forceinline__ const float* token_ptr(int r, int mode,
    const float* __restrict__ p0, const float* __restrict__ p1)
{
    if (mode == 0) {
        int b = r >> 12;
        int rem = r & 4095;
        int s = rem >> 4;
        int t = rem & 15;
        if (t < 8)  return p0 + ((size_t)((((b << 3) + t) << 8) + s) << 9);
        else        return p1 + ((size_t)((((b << 3) + (t - 8)) << 8) + s) << 9);
    } else {
        int b = r >> 4;
        int t = r & 15;
        if (t < 8)  return p0 + ((size_t)((b << 3) + t) << 9);
        else        return p1 + ((size_t)((b << 3) + (t - 8)) << 9);
    }
}

// ---------------------------------------------------------------------------
// Pre-conversion kernels
// ---------------------------------------------------------------------------
__global__ void __launch_bounds__(256) conv_tokens(
    const float* __restrict__ v_p, const float* __restrict__ v_f,
    const float* __restrict__ a_p, const float* __restrict__ a_f)
{
    int idx = blockIdx.x * 256 + threadIdx.x;    // one float4 per thread
    int row = idx >> 7;
    int c4  = (idx & 127) << 2;
    if (row >= MTOK) return;
    const float* src = (row < MV) ? token_ptr(row, 0, v_p, v_f)
                                  : token_ptr(row - MV, 1, a_p, a_f);
    float4 v = *(const float4*)(src + c4);
    __nv_bfloat16 h[4], l[4];
    cvt_hilo(v.x, h[0], l[0]); cvt_hilo(v.y, h[1], l[1]);
    cvt_hilo(v.z, h[2], l[2]); cvt_hilo(v.w, h[3], l[3]);
    size_t off = (size_t)row * D + c4;
    *(__nv_bfloat162*)(g_tok_hi + off)     = __nv_bfloat162(h[0], h[1]);
    *(__nv_bfloat162*)(g_tok_hi + off + 2) = __nv_bfloat162(h[2], h[3]);
    *(__nv_bfloat162*)(g_tok_lo + off)     = __nv_bfloat162(l[0], l[1]);
    *(__nv_bfloat162*)(g_tok_lo + off + 2) = __nv_bfloat162(l[2], l[3]);
}

__global__ void __launch_bounds__(256) conv_weights(
    const float* __restrict__ Wq, const float* __restrict__ Wp)
{
    int idx = blockIdx.x * 256 + threadIdx.x;    // one float4 per thread
    const int NQ4 = (D * NQKV) / 4;              // 196608
    const float* src;
    __nv_bfloat16 *dh, *dl;
    size_t off;
    if (idx < NQ4)      { src = Wq; dh = g_wq_hi; dl = g_wq_lo; off = (size_t)idx << 2; }
    else                { idx -= NQ4;
                          if (idx >= (D * D) / 4) return;
                          src = Wp; dh = g_wp_hi; dl = g_wp_lo; off = (size_t)idx << 2; }
    float4 v = *(const float4*)(src + off);
    __nv_bfloat16 h[4], l[4];
    cvt_hilo(v.x, h[0], l[0]); cvt_hilo(v.y, h[1], l[1]);
    cvt_hilo(v.z, h[2], l[2]); cvt_hilo(v.w, h[3], l[3]);
    *(__nv_bfloat162*)(dh + off)     = __nv_bfloat162(h[0], h[1]);
    *(__nv_bfloat162*)(dh + off + 2) = __nv_bfloat162(h[2], h[3]);
    *(__nv_bfloat162*)(dl + off)     = __nv_bfloat162(l[0], l[1]);
    *(__nv_bfloat162*)(dl + off + 2) = __nv_bfloat162(l[2], l[3]);
}

// RoPE sin/cos table: entry t*32+j = (sin, cos) of t * 10000^(-j/32)
__global__ void rope_table_kernel(void)
{
    int idx = threadIdx.x + blockIdx.x * 256;
    if (idx >= 1024) return;
    int t = idx >> 5;
    int j = idx & 31;
    float inv = exp2f(-0.41524101186091903f * (float)j);
    float ang = (float)t * inv;
    float sn, cs;
    sincosf(ang, &sn, &cs);
    g_rope[idx] = make_float2(sn, cs);
}

// ---------------------------------------------------------------------------
// Pipelined bf16x3 GEMM: 128x128 tile, BK=32, 2-stage cp.async, 256 threads.
// Stage layout (bytes): Ahi[128][40], Alo, Bhi[32][136], Blo
// ---------------------------------------------------------------------------
#define STG_A_HI   0
#define STG_A_LO   10240
#define STG_B_HI   20480
#define STG_B_LO   29184
#define STG_STRIDE 37888
#define SMEM_BYTES (2 * STG_STRIDE)
#define NSLAB      16

__device__ __forceinline__ void prefetch_slab(
    uint32_t stg,
    const __nv_bfloat16* __restrict__ Ahi, const __nv_bfloat16* __restrict__ Alo,
    const __nv_bfloat16* __restrict__ Bhi, const __nv_bfloat16* __restrict__ Blo,
    int ldb, int bn, int k0, int tid)
{
    #pragma unroll
    for (int t = 0; t < 2; ++t) {
        int q  = tid + (t << 8);              // 0..511
        int r  = q >> 2, kc = (q & 3) << 3;   // A: 128 rows x 4 chunks
        uint32_t ao = (uint32_t)(r * 80 + (kc << 1));
        size_t asrc = (size_t)r * D + k0 + kc;
        CP16(stg + STG_A_HI + ao, Ahi + asrc);
        CP16(stg + STG_A_LO + ao, Alo + asrc);
        int br = q >> 4, nc = (q & 15) << 3;  // B: 32 rows x 16 chunks
        uint32_t bo = (uint32_t)(br * 272 + (nc << 1));
        size_t bsrc = (size_t)(k0 + br) * ldb + bn + nc;
        CP16(stg + STG_B_HI + bo, Bhi + bsrc);
        CP16(stg + STG_B_LO + bo, Blo + bsrc);
    }
}

__device__ __forceinline__ void compute_slab(
    char* stg, int m0, int n0, int lane, float (&acc)[2][8][4])
{
    uint32_t ah[2][4], al[2][4], bh[8][2], bl[8][2];
    #pragma unroll
    for (int ks = 0; ks < 2; ++ks) {
        const int k0   = ks << 4;
        const int arow = lane & 15;
        const int acol = k0 + ((lane >> 4) << 3);
        #pragma unroll
        for (int mt = 0; mt < 2; ++mt) {
            uint32_t ad = smem_u32(stg + STG_A_HI + (m0 + (mt << 4) + arow) * 80 + acol * 2);
            LDSM_X4(ah[mt][0], ah[mt][1], ah[mt][2], ah[mt][3], ad);
            uint32_t ad2 = smem_u32(stg + STG_A_LO + (m0 + (mt << 4) + arow) * 80 + acol * 2);
            LDSM_X4(al[mt][0], al[mt][1], al[mt][2], al[mt][3], ad2);
        }
        #pragma unroll
        for (int p = 0; p < 4; ++p) {
            const int ncol = n0 + (p << 4) + ((lane >> 4) << 3);
            uint32_t bd = smem_u32(stg + STG_B_HI + (k0 + (lane & 15)) * 272 + ncol * 2);
            LDSM_X4_T(bh[2*p][0], bh[2*p][1], bh[2*p+1][0], bh[2*p+1][1], bd);
            uint32_t bd2 = smem_u32(stg + STG_B_LO + (k0 + (lane & 15)) * 272 + ncol * 2);
            LDSM_X4_T(bl[2*p][0], bl[2*p][1], bl[2*p+1][0], bl[2*p+1][1], bd2);
        }
        #pragma unroll
        for (int mt = 0; mt < 2; ++mt)
            #pragma unroll
            for (int nt = 0; nt < 8; ++nt) {
                MMA16816(acc[mt][nt], ah[mt], bh[nt]);
                MMA16816(acc[mt][nt], ah[mt], bl[nt]);
                MMA16816(acc[mt][nt], al[mt], bh[nt]);
            }
    }
}

#define GEMM_MAIN(AHI, ALO, BHI, BLO, LDB, BN)                                   \
    extern __shared__ char smem[];                                               \
    const uint32_t sbase = smem_u32(smem);                                       \
    const int tid  = threadIdx.x;                                                \
    const int lane = tid & 31;                                                   \
    const int w    = tid >> 5;                                                   \
    const int m0   = (w >> 1) << 5;                                              \
    const int n0   = (w & 1) << 6;                                               \
    float acc[2][8][4];                                                          \
    _Pragma("unroll")                                                            \
    for (int mt = 0; mt < 2; ++mt)                                               \
        _Pragma("unroll")                                                        \
        for (int nt = 0; nt < 8; ++nt)                                           \
            _Pragma("unroll")                                                    \
            for (int e = 0; e < 4; ++e) acc[mt][nt][e] = 0.f;                    \
    prefetch_slab(sbase, AHI, ALO, BHI, BLO, LDB, BN, 0, tid);                   \
    CP_COMMIT();                                                                 \
    for (int ks = 0; ks < NSLAB; ++ks) {                                         \
        if (ks + 1 < NSLAB) {                                                    \
            prefetch_slab(sbase + ((ks + 1) & 1) * STG_STRIDE,                   \
                          AHI, ALO, BHI, BLO, LDB, BN, (ks + 1) * 32, tid);      \
            CP_COMMIT();                                                         \
            CP_WAIT(1);                                                          \
        } else {                                                                 \
            CP_WAIT(0);                                                          \
        }                                                                        \
        __syncthreads();                                                         \
        compute_slab(smem + (ks & 1) * STG_STRIDE, m0, n0, lane, acc);           \
        __syncthreads();                                                         \
    }

// ---------------------------------------------------------------------------
// QKV GEMM: g_qkv[MTOK,1536] = tok[MTOKPAD,512] @ W_qkv[512,1536]
// ---------------------------------------------------------------------------
__global__ void __launch_bounds__(256) qkv_gemm(void)
{
    const int bm = blockIdx.y << 7;
    const int bn = blockIdx.x << 7;
    GEMM_MAIN(g_tok_hi + (size_t)bm * D, g_tok_lo + (size_t)bm * D,
              g_wq_hi, g_wq_lo, NQKV, bn)

    #pragma unroll
    for (int mt = 0; mt < 2; ++mt) {
        int r0 = bm + m0 + (mt << 4) + (lane >> 2);
        #pragma unroll
        for (int nt = 0; nt < 8; ++nt) {
            int c = bn + n0 + (nt << 3) + ((lane & 3) << 1);
            if (r0 < MTOK)
                *(float2*)(g_qkv + (size_t)r0 * NQKV + c) =
                    make_float2(acc[mt][nt][0], acc[mt][nt][1]);
            if (r0 + 8 < MTOK)
                *(float2*)(g_qkv + (size_t)(r0 + 8) * NQKV + c) =
                    make_float2(acc[mt][nt][2], acc[mt][nt][3]);
        }
    }
}

// ---------------------------------------------------------------------------
// Proj GEMM: (attn out)[32768,512] @ W_proj[512,512] + bias, fused scatter.
// ---------------------------------------------------------------------------
__device__ __forceinline__ void scatter_out(float* __restrict__ out, int r, int c, float v)
{
    int bs = r >> 5, t = r & 31, b = bs >> 8, s = bs & 255;
    if (t < 8) {
        out[((size_t)((((b << 3) + t) << 8) + s) << 9) + c] = v;
    } else if (t < 16) {
        out[OFF1 + ((size_t)((((b << 3) + (t - 8)) << 8) + s) << 9) + c] = v;
    } else if (t < 24) {
        atomicAdd(out + OFF2 + (((b << 3) + (t - 16)) << 9) + c, v * (1.f / 256.f));
    } else {
        atomicAdd(out + OFF3 + (((b << 3) + (t - 24)) << 9) + c, v * (1.f / 256.f));
    }
}

__global__ void __launch_bounds__(256) proj_gemm(
    const float* __restrict__ bias, float* __restrict__ out)
{
    const int bm = blockIdx.y << 7;
    const int bn = blockIdx.x << 7;
    GEMM_MAIN(g_o_hi + (size_t)bm * D, g_o_lo + (size_t)bm * D,
              g_wp_hi, g_wp_lo, D, bn)

    #pragma unroll
    for (int mt = 0; mt < 2; ++mt) {
        int r0 = bm + m0 + (mt << 4) + (lane >> 2);
        #pragma unroll
        for (int nt = 0; nt < 8; ++nt) {
            int c = bn + n0 + (nt << 3) + ((lane & 3) << 1);
            float b0 = bias[c], b1 = bias[c + 1];
            scatter_out(out, r0,     c,     acc[mt][nt][0] + b0);
            scatter_out(out, r0,     c + 1, acc[mt][nt][1] + b1);
            scatter_out(out, r0 + 8, c,     acc[mt][nt][2] + b0);
            scatter_out(out, r0 + 8, c + 1, acc[mt][nt][3] + b1);
        }
    }
}

// ---------------------------------------------------------------------------
// Attention (tensor-core, register-direct staging):
// one block per (bs, head), 128 threads (4 warps).
// Phase 1 loads Q/K/V straight to registers, applies RoPE from the table,
// converts to bf16 hi/lo, and stores ONCE into the MMA tiles. 3 barriers.
// Smem (bytes): QH/QL [32][72] @ 0/4608; KTH/KTL [64][40] @ 9216/14336;
//               VH/VL [32][72] @ 19456/24064; PH/PL [32][40] @ 28672/31232;
//               Ss [32][33] f32 @ 33792. Total 38016.
// ---------------------------------------------------------------------------
#define A_QH  0
#define A_QL  4608
#define A_KTH 9216
#define A_KTL 14336
#define A_VH  19456
#define A_VL  24064
#define A_PH  28672
#define A_PL  31232
#define A_SS  33792
#define ATT_SMEM 38016

__global__ void __launch_bounds__(128) attn_kernel()
{
    extern __shared__ char asm_[];
    __nv_bfloat16* QH = (__nv_bfloat16*)(asm_ + A_QH);   // [32][72]
    __nv_bfloat16* QL = (__nv_bfloat16*)(asm_ + A_QL);
    __nv_bfloat16* KTH = (__nv_bfloat16*)(asm_ + A_KTH); // [64][40]
    __nv_bfloat16* KTL = (__nv_bfloat16*)(asm_ + A_KTL);
    __nv_bfloat16* VH = (__nv_bfloat16*)(asm_ + A_VH);   // [32][72]
    __nv_bfloat16* VL = (__nv_bfloat16*)(asm_ + A_VL);
    __nv_bfloat16* PH = (__nv_bfloat16*)(asm_ + A_PH);   // [32][40]
    __nv_bfloat16* PL = (__nv_bfloat16*)(asm_ + A_PL);
    float* Ss = (float*)(asm_ + A_SS);                   // [32][33]

    const int tid  = threadIdx.x;
    const int lane = tid & 31;
    const int w    = tid >> 5;
    const int bh   = blockIdx.x;
    const int bs   = bh >> 3;
    const int h    = bh & 7;
    const int b    = bs >> 8;

    // Phase 1: direct LDG -> RoPE -> cvt -> STS (bf16 tiles only)
    #pragma unroll
    for (int p = 0; p < 2; ++p) {
        int idx = tid + (p << 7);         // 0..255
        int t   = idx >> 3;               // 0..31 row
        int c4  = (idx & 7) << 2;         // 0,4,..,28 (first half col)
        int row = (t < 16) ? ((bs << 4) + t) : (MV + (b << 4) + (t - 16));
        const float* qp = g_qkv + (size_t)row * NQKV + (h << 6);
        float4 qa4 = *(const float4*)(qp + c4);
        float4 qb4 = *(const float4*)(qp + c4 + 32);
        float4 ka4 = *(const float4*)(qp + 512 + c4);
        float4 kb4 = *(const float4*)(qp + 512 + c4 + 32);
        float4 va4 = *(const float4*)(qp + 1024 + c4);
        float4 vb4 = *(const float4*)(qp + 1024 + c4 + 32);
        float qa[4] = {qa4.x, qa4.y, qa4.z, qa4.w};
        float qb[4] = {qb4.x, qb4.y, qb4.z, qb4.w};
        float ka[4] = {ka4.x, ka4.y, ka4.z, ka4.w};
        float kb[4] = {kb4.x, kb4.y, kb4.z, kb4.w};

        #pragma unroll
        for (int e = 0; e < 4; ++e) {
            float2 sc = g_rope[(t << 5) + c4 + e];
            float sn = sc.x, cs = sc.y;
            float q1 = qa[e], q2 = qb[e];
            qa[e] = q1 * cs - q2 * sn;
            qb[e] = q2 * cs + q1 * sn;
            float k1 = ka[e], k2 = kb[e];
            ka[e] = k1 * cs - k2 * sn;
            kb[e] = k2 * cs + k1 * sn;
        }

        // Q: row-major bf16 hi/lo stores (bf162 pairs)
        {
            __nv_bfloat16 h0,l0,h1,l1,h2,l2,h3,l3;
            cvt_hilo(qa[0], h0, l0); cvt_hilo(qa[1], h1, l1);
            cvt_hilo(qa[2], h2, l2); cvt_hilo(qa[3], h3, l3);
            *(__nv_bfloat162*)(QH + t*72 + c4)     = __nv_bfloat162(h0, h1);
            *(__nv_bfloat162*)(QH + t*72 + c4 + 2) = __nv_bfloat162(h2, h3);
            *(__nv_bfloat162*)(QL + t*72 + c4)     = __nv_bfloat162(l0, l1);
            *(__nv_bfloat162*)(QL + t*72 + c4 + 2) = __nv_bfloat162(l2, l3);
            cvt_hilo(qb[0], h0, l0); cvt_hilo(qb[1], h1, l1);
            cvt_hilo(qb[2], h2, l2); cvt_hilo(qb[3], h3, l3);
            *(__nv_bfloat162*)(QH + t*72 + c4 + 32) = __nv_bfloat162(h0, h1);
            *(__nv_bfloat162*)(QH + t*72 + c4 + 34) = __nv_bfloat162(h2, h3);
            *(__nv_bfloat162*)(QL + t*72 + c4 + 32) = __nv_bfloat162(l0, l1);
            *(__nv_bfloat162*)(QL + t*72 + c4 + 34) = __nv_bfloat162(l2, l3);
        }
        // K: transposed scalar stores
        #pragma unroll
        for (int e = 0; e < 4; ++e) {
            __nv_bfloat16 hh, ll;
            cvt_hilo(ka[e], hh, ll);
            KTH[(c4 + e)*40 + t] = hh;
            KTL[(c4 + e)*40 + t] = ll;
            cvt_hilo(kb[e], hh, ll);
            KTH[(c4 + 32 + e)*40 + t] = hh;
            KTL[(c4 + 32 + e)*40 + t] = ll;
        }
        // V: row-major bf16 hi/lo
        {
            __nv_bfloat16 h0,l0,h1,l1,h2,l2,h3,l3;
            cvt_hilo(va4.x, h0, l0); cvt_hilo(va4.y, h1, l1);
            cvt_hilo(va4.z, h2, l2); cvt_hilo(va4.w, h3, l3);
            *(__nv_bfloat162*)(VH + t*72 + c4)     = __nv_bfloat162(h0, h1);
            *(__nv_bfloat162*)(VH + t*72 + c4 + 2) = __nv_bfloat162(h2, h3);
            *(__nv_bfloat162*)(VL + t*72 + c4)     = __nv_bfloat162(l0, l1);
            *(__nv_bfloat162*)(VL + t*72 + c4 + 2) = __nv_bfloat162(l2, l3);
            cvt_hilo(vb4.x, h0, l0); cvt_hilo(vb4.y, h1, l1);
            cvt_hilo(vb4.z, h2, l2); cvt_hilo(vb4.w, h3, l3);
            *(__nv_bfloat162*)(VH + t*72 + c4 + 32) = __nv_bfloat162(h0, h1);
            *(__nv_bfloat162*)(VH + t*72 + c4 + 34) = __nv_bfloat162(h2, h3);
            *(__nv_bfloat162*)(VL + t*72 + c4 + 32) = __nv_bfloat162(l0, l1);
            *(__nv_bfloat162*)(VL + t*72 + c4 + 34) = __nv_bfloat162(l2, l3);
        }
    }
    __syncthreads();

    // Phase 2: S = QK^T * scale via MMA. Warp w: m0=(w&1)*16, n0=(w>>1)*16.
    {
        const int m0 = (w & 1) << 4;
        const int n0 = (w >> 1) << 4;
        float sacc[2][4] = {{0.f,0.f,0.f,0.f},{0.f,0.f,0.f,0.f}};
        uint32_t ah[4], al[4], bhf[2][2], blf[2][2];
        #pragma unroll
        for (int kc = 0; kc < 4; ++kc) {
            const int k0 = kc << 4;
            const int arow = m0 + (lane & 15);
            const int acol = k0 + ((lane >> 4) << 3);
            LDSM_X4(ah[0], ah[1], ah[2], ah[3], smem_u32(QH + arow*72 + acol));
            LDSM_X4(al[0], al[1], al[2], al[3], smem_u32(QL + arow*72 + acol));
            const int brow = k0 + (lane & 15);
            const int bcol = n0 + ((lane >> 4) << 3);
            LDSM_X4_T(bhf[0][0], bhf[0][1], bhf[1][0], bhf[1][1], smem_u32(KTH + brow*40 + bcol));
            LDSM_X4_T(blf[0][0], blf[0][1], blf[1][0], blf[1][1], smem_u32(KTL + brow*40 + bcol));
            #pragma unroll
            for (int nt = 0; nt < 2; ++nt) {
                MMA16816(sacc[nt], ah, bhf[nt]);
                MMA16816(sacc[nt], ah, blf[nt]);
                MMA16816(sacc[nt], al, bhf[nt]);
            }
        }
        const int r0 = m0 + (lane >> 2);
        #pragma unroll
        for (int nt = 0; nt < 2; ++nt) {
            int c = n0 + (nt << 3) + ((lane & 3) << 1);
            Ss[r0*33 + c]       = sacc[nt][0] * 0.125f;
            Ss[r0*33 + c + 1]   = sacc[nt][1] * 0.125f;
            Ss[(r0+8)*33 + c]     = sacc[nt][2] * 0.125f;
            Ss[(r0+8)*33 + c + 1] = sacc[nt][3] * 0.125f;
        }
    }
    __syncthreads();

    // Phase 3: row softmax; emit P as bf16 hi/lo directly
    #pragma unroll
    for (int rr = 0; rr < 8; ++rr) {
        int i = (w << 3) + rr;
        float val = Ss[i*33 + lane];
        float m = val;
        #pragma unroll
        for (int o = 16; o > 0; o >>= 1) m = fmaxf(m, __shfl_xor_sync(0xffffffffu, m, o));
        float e = expf(val - m);
        float sum = e;
        #pragma unroll
        for (int o = 16; o > 0; o >>= 1) sum += __shfl_xor_sync(0xffffffffu, sum, o);
        float pv = e / sum;
        __nv_bfloat16 hh, ll;
        cvt_hilo(pv, hh, ll);
        PH[i*40 + lane] = hh;
        PL[i*40 + lane] = ll;
    }
    __syncthreads();

    // Phase 4: O = P @ V via MMA. Warp w: m0=(w&1)*16, n0=(w>>1)*32.
    {
        const int m0 = (w & 1) << 4;
        const int n0 = (w >> 1) << 5;
        float oacc[4][4];
        #pragma unroll
        for (int nt = 0; nt < 4; ++nt)
            #pragma unroll
            for (int e = 0; e < 4; ++e) oacc[nt][e] = 0.f;
        uint32_t ah[4], al[4], bhf[4][2], blf[4][2];
        #pragma unroll
        for (int kc = 0; kc < 2; ++kc) {
            const int k0 = kc << 4;
            const int arow = m0 + (lane & 15);
            const int acol = k0 + ((lane >> 4) << 3);
            LDSM_X4(ah[0], ah[1], ah[2], ah[3], smem_u32(PH + arow*40 + acol));
            LDSM_X4(al[0], al[1], al[2], al[3], smem_u32(PL + arow*40 + acol));
            #pragma unroll
            for (int p = 0; p < 2; ++p) {
                const int brow = k0 + (lane & 15);
                const int bcol = n0 + (p << 4) + ((lane >> 4) << 3);
                LDSM_X4_T(bhf[2*p][0], bhf[2*p][1], bhf[2*p+1][0], bhf[2*p+1][1],
                          smem_u32(VH + brow*72 + bcol));
                LDSM_X4_T(blf[2*p][0], blf[2*p][1], blf[2*p+1][0], blf[2*p+1][1],
                          smem_u32(VL + brow*72 + bcol));
            }
            #pragma unroll
            for (int nt = 0; nt < 4; ++nt) {
                MMA16816(oacc[nt], ah, bhf[nt]);
                MMA16816(oacc[nt], ah, blf[nt]);
                MMA16816(oacc[nt], al, bhf[nt]);
            }
        }
        // Epilogue: cvt + store bf16 hi/lo
        const int r0 = m0 + (lane >> 2);
        #pragma unroll
        for (int nt = 0; nt < 4; ++nt) {
            int c = n0 + (nt << 3) + ((lane & 3) << 1);
            size_t o0 = (size_t)((bs << 5) + r0) * D + (h << 6) + c;
            size_t o1 = (size_t)((bs << 5) + r0 + 8) * D + (h << 6) + c;
            __nv_bfloat16 h0,l0,h1,l1,h2,l2,h3,l3;
            cvt_hilo(oacc[nt][0], h0, l0); cvt_hilo(oacc[nt][1], h1, l1);
            cvt_hilo(oacc[nt][2], h2, l2); cvt_hilo(oacc[nt][3], h3, l3);
            *(__nv_bfloat162*)(g_o_hi + o0) = __nv_bfloat162(h0, h1);
            *(__nv_bfloat162*)(g_o_lo + o0) = __nv_bfloat162(l0, l1);
            *(__nv_bfloat162*)(g_o_hi + o1) = __nv_bfloat162(h2, h3);
            *(__nv_bfloat162*)(g_o_lo + o1) = __nv_bfloat162(l2, l3);
        }
    }
}

// ---------------------------------------------------------------------------
__global__ void zero_tail_kernel(float* __restrict__ out)
{
    int i = blockIdx.x * 256 + threadIdx.x;
    if (i < 32768) out[OFF2 + i] = 0.f;
}

// ---------------------------------------------------------------------------
extern "C" void kernel_launch(void* const* d_in, const int* in_sizes, int n_in,
                              void* d_out, int out_size)
{
    const float* v_p    = (const float*)d_in[0];
    const float* v_f    = (const float*)d_in[1];
    const float* a_p    = (const float*)d_in[2];
    const float* a_f    = (const float*)d_in[3];
    const float* W_qkv  = (const float*)d_in[4];
    const float* W_proj = (const float*)d_in[5];
    const float* b_proj = (const float*)d_in[6];
    float* out = (float*)d_out;

    cudaFuncSetAttribute(qkv_gemm,  cudaFuncAttributeMaxDynamicSharedMemorySize, SMEM_BYTES);
    cudaFuncSetAttribute(proj_gemm, cudaFuncAttributeMaxDynamicSharedMemorySize, SMEM_BYTES);
    cudaFuncSetAttribute(attn_kernel, cudaFuncAttributeMaxDynamicSharedMemorySize, ATT_SMEM);

    rope_table_kernel<<<4, 256>>>();
    conv_weights<<<1024, 256>>>(W_qkv, W_proj);
    conv_tokens<<<8224, 256>>>(v_p, v_f, a_p, a_f);

    qkv_gemm<<<dim3(12, 129), 256, SMEM_BYTES>>>();

    attn_kernel<<<8192, 128, ATT_SMEM>>>();

    zero_tail_kernel<<<128, 256>>>(out);
    proj_gemm<<<dim3(4, 256), 256, SMEM_BYTES>>>(b_proj, out);
}